// round 1
// baseline (speedup 1.0000x reference)
#include <cuda_runtime.h>
#include <math.h>

// Problem constants
#define PW 49        // tokens per window (7x7)
#define DD 128       // feature dim
#define NHH 4        // heads
#define DHH 32       // head dim
#define QC 384       // qkv output cols
#define QP 385       // qkv smem pitch (odd -> conflict-free column access)

// Shared memory layout (floats)
//   xs   : [49][128]  = 6272   (x input; reused as attention-output buffer)
//   qkv  : [49][385]  = 18865
//   wt   : [64][32]   = 2048   (weight staging tile)
//   tb   : [169*4]    = 676    (relative position bias table)
static constexpr int XS_OFF  = 0;
static constexpr int QKV_OFF = 6272;
static constexpr int WT_OFF  = QKV_OFF + 18865;           // 25137
static constexpr int TB_OFF  = WT_OFF + 2048;             // 27185
static constexpr int SMEM_FLOATS = TB_OFF + 676;          // 27861
static constexpr int SMEM_BYTES  = SMEM_FLOATS * 4;       // 111444 -> 2 CTAs/SM

__global__ void __launch_bounds__(256, 2)
rpmha_fp32_kernel(const float* __restrict__ x,
                  const float* __restrict__ Wqkv,
                  const float* __restrict__ bqkv,
                  const float* __restrict__ Wmerge,
                  const float* __restrict__ bmerge,
                  const float* __restrict__ table,
                  float* __restrict__ out)
{
    extern __shared__ float sm[];
    float* xs  = sm + XS_OFF;
    float* qkv = sm + QKV_OFF;
    float* wt  = sm + WT_OFF;
    float* tb  = sm + TB_OFF;

    const int w    = blockIdx.x;
    const int tid  = threadIdx.x;
    const int warp = tid >> 5;
    const int lane = tid & 31;

    // ---- load x window (6272 floats) + bias table into smem ----
    {
        const float4* xg  = reinterpret_cast<const float4*>(x + (size_t)w * (PW * DD));
        float4*       xs4 = reinterpret_cast<float4*>(xs);
        #pragma unroll 2
        for (int i = tid; i < (PW * DD) / 4; i += 256) xs4[i] = xg[i];
        for (int i = tid; i < 676; i += 256) tb[i] = table[i];
    }
    __syncthreads();

    // Row assignment for GEMM phases: warp w handles rows [7w, 7w+7), clamped
    // reads for rows >= 49 (stores guarded).
    const int r0 = warp * 7;
    const float* xrow[7];
    #pragma unroll
    for (int r = 0; r < 7; r++) {
        int rr = r0 + r; if (rr > PW - 1) rr = PW - 1;
        xrow[r] = xs + rr * DD;
    }

    const float scale = 0.17677669529663687f;  // 1/sqrt(32)

    // ================= Phase 2: qkv = x @ Wqkv + bqkv (q pre-scaled) =========
    for (int ct = 0; ct < 12; ct++) {
        const int c = ct * 32 + lane;
        float acc[7];
        {
            float bb = __ldg(bqkv + c);
            #pragma unroll
            for (int r = 0; r < 7; r++) acc[r] = bb;
        }
        for (int kc = 0; kc < 2; kc++) {
            __syncthreads();   // previous wt consumers done
            #pragma unroll
            for (int m = 0; m < 8; m++) {
                int kk = warp * 8 + m;
                wt[kk * 32 + lane] = __ldg(Wqkv + (size_t)(kc * 64 + kk) * QC + c);
            }
            __syncthreads();
            const int kb = kc * 64;
            #pragma unroll 8
            for (int kk = 0; kk < 64; kk++) {
                float wv = wt[kk * 32 + lane];
                #pragma unroll
                for (int r = 0; r < 7; r++)
                    acc[r] = fmaf(xrow[r][kb + kk], wv, acc[r]);
            }
        }
        const float mul = (c < DD) ? scale : 1.0f;  // scale q part only
        #pragma unroll
        for (int r = 0; r < 7; r++) {
            int rr = r0 + r;
            if (rr < PW) qkv[rr * QP + c] = acc[r] * mul;
        }
    }
    __syncthreads();

    // ================= Phase 3: attention (per-(row,head) warp task) =========
    // warp handles (i, h): logits (49) in 2 regs/lane, softmax via shfl,
    // AV via shfl-broadcast. Output into xs (x no longer needed).
    for (int t = warp; t < PW * NHH; t += 8) {
        const int h    = t & 3;
        const int i    = t >> 2;
        const int hoff = h * DHH;

        const float* qrow = qkv + i * QP + hoff;
        const int j2     = lane + 32;
        const bool has2  = (j2 < PW);
        const int  j2c   = has2 ? j2 : (PW - 1);
        const float* k1  = qkv + lane * QP + DD + hoff;
        const float* k2  = qkv + j2c  * QP + DD + hoff;

        float l1 = 0.f, l2 = 0.f;
        #pragma unroll
        for (int d = 0; d < DHH; d++) {
            float qd = qrow[d];
            l1 = fmaf(qd, k1[d], l1);
            l2 = fmaf(qd, k2[d], l2);
        }

        // relative position bias: idx = ((ri-rj)+6)*13 + ((ci-cj)+6)
        const int ri = i / 7, ci = i - ri * 7;
        {
            int rj = lane / 7, cj = lane - rj * 7;
            l1 += tb[(((ri - rj + 6) * 13) + (ci - cj + 6)) * NHH + h];
        }
        if (has2) {
            int rj = j2 / 7, cj = j2 - rj * 7;
            l2 += tb[(((ri - rj + 6) * 13) + (ci - cj + 6)) * NHH + h];
        } else {
            l2 = -1e30f;
        }

        // softmax over 49 logits spread across the warp
        float m = fmaxf(l1, l2);
        #pragma unroll
        for (int o = 16; o > 0; o >>= 1)
            m = fmaxf(m, __shfl_xor_sync(0xffffffffu, m, o));
        float p1 = expf(l1 - m);
        float p2 = has2 ? expf(l2 - m) : 0.f;
        float s = p1 + p2;
        #pragma unroll
        for (int o = 16; o > 0; o >>= 1)
            s += __shfl_xor_sync(0xffffffffu, s, o);
        const float inv = 1.0f / s;
        p1 *= inv; p2 *= inv;

        // out[i, hoff+lane] = sum_j p_j * v[j, hoff+lane]
        float acc = 0.f;
        const float* vb = qkv + 2 * DD + hoff + lane;
        #pragma unroll
        for (int j = 0; j < PW; j++) {
            float p = (j < 32) ? __shfl_sync(0xffffffffu, p1, j)
                               : __shfl_sync(0xffffffffu, p2, j - 32);
            acc = fmaf(p, vb[j * QP], acc);
        }
        xs[i * DD + hoff + lane] = acc;
    }
    __syncthreads();

    // ================= Phase 4: out = attn_out @ Wmerge + bmerge =============
    const size_t obase = (size_t)w * (PW * DD);
    for (int ct = 0; ct < 4; ct++) {
        const int c = ct * 32 + lane;
        float acc[7];
        {
            float bb = __ldg(bmerge + c);
            #pragma unroll
            for (int r = 0; r < 7; r++) acc[r] = bb;
        }
        for (int kc = 0; kc < 2; kc++) {
            __syncthreads();
            #pragma unroll
            for (int m = 0; m < 8; m++) {
                int kk = warp * 8 + m;
                wt[kk * 32 + lane] = __ldg(Wmerge + (size_t)(kc * 64 + kk) * DD + c);
            }
            __syncthreads();
            const int kb = kc * 64;
            #pragma unroll 8
            for (int kk = 0; kk < 64; kk++) {
                float wv = wt[kk * 32 + lane];
                #pragma unroll
                for (int r = 0; r < 7; r++)
                    acc[r] = fmaf(xrow[r][kb + kk], wv, acc[r]);  // xs == attn out
            }
        }
        #pragma unroll
        for (int r = 0; r < 7; r++) {
            int rr = r0 + r;
            if (rr < PW) out[obase + rr * DD + c] = acc[r];
        }
    }
}

extern "C" void kernel_launch(void* const* d_in, const int* in_sizes, int n_in,
                              void* d_out, int out_size)
{
    const float* x      = (const float*)d_in[0];
    const float* Wqkv   = (const float*)d_in[1];
    const float* bqkv   = (const float*)d_in[2];
    const float* Wmerge = (const float*)d_in[3];
    const float* bmerge = (const float*)d_in[4];
    const float* table  = (const float*)d_in[5];
    float* out = (float*)d_out;

    const int nwin = in_sizes[0] / (PW * DD);  // B*G = 16384

    cudaFuncSetAttribute(rpmha_fp32_kernel,
                         cudaFuncAttributeMaxDynamicSharedMemorySize, SMEM_BYTES);
    rpmha_fp32_kernel<<<nwin, 256, SMEM_BYTES>>>(x, Wqkv, bqkv, Wmerge, bmerge,
                                                 table, out);
}

// round 3
// speedup vs baseline: 7.3761x; 7.3761x over previous
#include <cuda_runtime.h>
#include <cuda_fp16.h>
#include <cstdint>
#include <math.h>

#define PW 49        // tokens per window
#define DD 128       // feature dim

// fp16 weight caches (converted once per launch by a prep kernel)
__device__ __half g_wqkv[128 * 384];
__device__ __half g_wmerge[128 * 128];

__global__ void convert_w_kernel(const float* __restrict__ wq,
                                 const float* __restrict__ wm)
{
    int i = blockIdx.x * 256 + threadIdx.x;
    if (i < 128 * 384) g_wqkv[i]   = __float2half_rn(wq[i]);
    if (i < 128 * 128) g_wmerge[i] = __float2half_rn(wm[i]);
}

// ---------------- smem layout (in halfs) ----------------
// xh   : [128][136]  x input (2 windows, rows 49..63 of each zeroed);
//                    reused as attention-output buffer
// qkv  : [128][392]  fp16 qkv (q pre-scaled)
// wbuf : [128][72]   weight chunk staging (64 cols)
// tb   : 676 fp32    relative-position bias table
static constexpr int XH_P   = 136;
static constexpr int QKV_P  = 392;
static constexpr int WB_P   = 72;
static constexpr int XH_OFF  = 0;
static constexpr int QKV_OFF = 128 * XH_P;            // 17408
static constexpr int WB_OFF  = QKV_OFF + 128 * QKV_P; // 67584
static constexpr int HALFS   = WB_OFF + 128 * WB_P;   // 76800
static constexpr int SMEM_BYTES = HALFS * 2 + 676 * 4; // 156304

__device__ __forceinline__ uint32_t cvta_s(const void* p)
{
    return (uint32_t)__cvta_generic_to_shared(p);
}
__device__ __forceinline__ uint32_t f2h2(float a, float b)
{
    __half2 h = __floats2half2_rn(a, b);
    return *reinterpret_cast<uint32_t*>(&h);
}

#define LDSM4(R0,R1,R2,R3,ADDR) \
    asm volatile("ldmatrix.sync.aligned.m8n8.x4.shared.b16 {%0,%1,%2,%3},[%4];" \
        : "=r"(R0),"=r"(R1),"=r"(R2),"=r"(R3) : "r"(ADDR))
#define LDSM4T(R0,R1,R2,R3,ADDR) \
    asm volatile("ldmatrix.sync.aligned.m8n8.x4.trans.shared.b16 {%0,%1,%2,%3},[%4];" \
        : "=r"(R0),"=r"(R1),"=r"(R2),"=r"(R3) : "r"(ADDR))
#define MMA(C0,C1,C2,C3,A0,A1,A2,A3,B0,B1) \
    asm volatile("mma.sync.aligned.m16n8k16.row.col.f32.f16.f16.f32 " \
        "{%0,%1,%2,%3},{%4,%5,%6,%7},{%8,%9},{%0,%1,%2,%3};" \
        : "+f"(C0),"+f"(C1),"+f"(C2),"+f"(C3) \
        : "r"(A0),"r"(A1),"r"(A2),"r"(A3),"r"(B0),"r"(B1))

__global__ void __launch_bounds__(256, 1)
rpmha_mma_kernel(const float* __restrict__ x,
                 const float* __restrict__ bqkv,
                 const float* __restrict__ bmerge,
                 const float* __restrict__ table,
                 float* __restrict__ out)
{
    extern __shared__ __half sh[];
    __half* xh   = sh + XH_OFF;
    __half* qkv  = sh + QKV_OFF;
    __half* wbuf = sh + WB_OFF;
    float*  tb   = reinterpret_cast<float*>(sh + HALFS);

    const int tid = threadIdx.x, warp = tid >> 5, lane = tid & 31;
    const size_t xbase = (size_t)blockIdx.x * 2u * (PW * DD);

    // ---- load 2 windows of x -> fp16 smem (pad rows zeroed) + bias table ----
    #pragma unroll 4
    for (int idx = tid; idx < 4096; idx += 256) {
        int row = idx >> 5, c4 = (idx & 31) << 2;
        int v = row >> 6, i = row & 63;
        uint2 st;
        if (i < PW) {
            float4 f = *reinterpret_cast<const float4*>(
                x + xbase + (size_t)v * (PW * DD) + i * DD + c4);
            st.x = f2h2(f.x, f.y); st.y = f2h2(f.z, f.w);
        } else { st.x = 0u; st.y = 0u; }
        *reinterpret_cast<uint2*>(xh + row * XH_P + c4) = st;
    }
    for (int i = tid; i < 676; i += 256) tb[i] = table[i];
    __syncthreads();

    const uint32_t xh_s  = cvta_s(xh);
    const uint32_t qkv_s = cvta_s(qkv);
    const uint32_t wb_s  = cvta_s(wbuf);
    const float scale = 0.17677669529663687f;  // 1/sqrt(32)

    // ---- persistent A fragments: x rows [16*warp, 16*warp+16), K=128 ----
    uint32_t af[8][4];
    {
        uint32_t a0 = xh_s + (((warp << 4) + (lane & 15)) * XH_P + ((lane >> 4) << 3)) * 2;
        #pragma unroll
        for (int kk = 0; kk < 8; kk++)
            LDSM4(af[kk][0], af[kk][1], af[kk][2], af[kk][3], a0 + kk * 32);
    }

    // ================= Phase 1: qkv = x @ Wqkv + bqkv =================
    for (int cn = 0; cn < 6; cn++) {
        __syncthreads();
        #pragma unroll
        for (int i2 = tid; i2 < 2048; i2 += 256) {
            int r = i2 >> 4, c4 = (i2 & 15) << 2;
            *reinterpret_cast<uint2*>(wbuf + r * WB_P + c4) =
                *reinterpret_cast<const uint2*>(g_wqkv + r * 384 + cn * 64 + c4);
        }
        __syncthreads();

        float acc[8][4];
        #pragma unroll
        for (int nt = 0; nt < 8; nt++) {
            int col = cn * 64 + nt * 8 + ((lane & 3) << 1);
            acc[nt][0] = __ldg(bqkv + col);
            acc[nt][1] = __ldg(bqkv + col + 1);
            acc[nt][2] = acc[nt][0];
            acc[nt][3] = acc[nt][1];
        }
        uint32_t wb0 = wb_s + ((lane & 15) * WB_P + ((lane >> 4) << 3)) * 2;
        #pragma unroll
        for (int kk = 0; kk < 8; kk++) {
            uint32_t b[4][4];
            #pragma unroll
            for (int np = 0; np < 4; np++)
                LDSM4T(b[np][0], b[np][1], b[np][2], b[np][3],
                       wb0 + (kk * 16 * WB_P + np * 16) * 2);
            #pragma unroll
            for (int np = 0; np < 4; np++) {
                MMA(acc[2*np][0],acc[2*np][1],acc[2*np][2],acc[2*np][3],
                    af[kk][0],af[kk][1],af[kk][2],af[kk][3], b[np][0], b[np][1]);
                MMA(acc[2*np+1][0],acc[2*np+1][1],acc[2*np+1][2],acc[2*np+1][3],
                    af[kk][0],af[kk][1],af[kk][2],af[kk][3], b[np][2], b[np][3]);
            }
        }
        const float mul = (cn < 2) ? scale : 1.0f;  // q cols < 128 pre-scaled
        const int row = (warp << 4) + (lane >> 2);
        #pragma unroll
        for (int nt = 0; nt < 8; nt++) {
            int col = cn * 64 + nt * 8 + ((lane & 3) << 1);
            *reinterpret_cast<__half2*>(qkv + row * QKV_P + col) =
                __floats2half2_rn(acc[nt][0] * mul, acc[nt][1] * mul);
            *reinterpret_cast<__half2*>(qkv + (row + 8) * QKV_P + col) =
                __floats2half2_rn(acc[nt][2] * mul, acc[nt][3] * mul);
        }
    }
    __syncthreads();

    // ================= Phase 2: attention, warp = (window, head) =============
    {
        const int v = warp >> 2, h = warp & 3;
        const int rbase = v << 6;

        // K as B fragments: 7 n-tiles (tokens) x 2 k-steps (d)
        uint32_t kb[7][4];
        #pragma unroll
        for (int nt = 0; nt < 7; nt++) {
            uint32_t addr = qkv_s + ((rbase + nt * 8 + (lane & 7)) * QKV_P
                                     + 128 + h * 32 + ((lane >> 3) << 3)) * 2;
            LDSM4(kb[nt][0], kb[nt][1], kb[nt][2], kb[nt][3], addr);
        }
        // V as B fragments: 4 k-steps (tokens) x 4 n-tiles (d)
        uint32_t vb[4][8];
        #pragma unroll
        for (int kt = 0; kt < 4; kt++)
            #pragma unroll
            for (int dp = 0; dp < 2; dp++) {
                uint32_t addr = qkv_s + ((rbase + kt * 16 + (lane & 15)) * QKV_P
                                         + 256 + h * 32 + dp * 16 + ((lane >> 4) << 3)) * 2;
                LDSM4T(vb[kt][dp*4+0], vb[kt][dp*4+1], vb[kt][dp*4+2], vb[kt][dp*4+3], addr);
            }

        #pragma unroll
        for (int m = 0; m < 4; m++) {
            // Q A-fragments for this 16-row block (2 k-steps over d=32)
            uint32_t qa[4], qa2[4];
            uint32_t qaddr = qkv_s + ((rbase + m * 16 + (lane & 15)) * QKV_P
                                      + h * 32 + ((lane >> 4) << 3)) * 2;
            LDSM4(qa[0], qa[1], qa[2], qa[3], qaddr);
            LDSM4(qa2[0], qa2[1], qa2[2], qa2[3], qaddr + 32);

            float s[7][4];
            #pragma unroll
            for (int nt = 0; nt < 7; nt++) {
                s[nt][0] = s[nt][1] = s[nt][2] = s[nt][3] = 0.f;
                MMA(s[nt][0],s[nt][1],s[nt][2],s[nt][3],
                    qa[0],qa[1],qa[2],qa[3], kb[nt][0], kb[nt][1]);
                MMA(s[nt][0],s[nt][1],s[nt][2],s[nt][3],
                    qa2[0],qa2[1],qa2[2],qa2[3], kb[nt][2], kb[nt][3]);
            }

            // relative position bias + j-mask
            int i0 = m * 16 + (lane >> 2), i1 = i0 + 8;
            int i0c = (i0 < PW) ? i0 : 0, i1c = (i1 < PW) ? i1 : 0;
            int r0 = (i0c * 147) >> 10, c0i = i0c - r0 * 7;
            int r1 = (i1c * 147) >> 10, c1i = i1c - r1 * 7;
            #pragma unroll
            for (int nt = 0; nt < 7; nt++) {
                #pragma unroll
                for (int e = 0; e < 2; e++) {
                    int j = nt * 8 + ((lane & 3) << 1) + e;
                    if (j < PW) {
                        int rj = (j * 147) >> 10, cj = j - rj * 7;
                        s[nt][e]   += tb[(((r0 - rj + 6) * 13) + (c0i - cj + 6)) * 4 + h];
                        s[nt][2+e] += tb[(((r1 - rj + 6) * 13) + (c1i - cj + 6)) * 4 + h];
                    } else {
                        s[nt][e] = -1e30f; s[nt][2+e] = -1e30f;
                    }
                }
            }

            // softmax: rows i0 (elems 0,1) / i1 (elems 2,3), quad shfl reduce
            float ml = -1e30f, mh = -1e30f;
            #pragma unroll
            for (int nt = 0; nt < 7; nt++) {
                ml = fmaxf(ml, fmaxf(s[nt][0], s[nt][1]));
                mh = fmaxf(mh, fmaxf(s[nt][2], s[nt][3]));
            }
            ml = fmaxf(ml, __shfl_xor_sync(0xffffffffu, ml, 1));
            ml = fmaxf(ml, __shfl_xor_sync(0xffffffffu, ml, 2));
            mh = fmaxf(mh, __shfl_xor_sync(0xffffffffu, mh, 1));
            mh = fmaxf(mh, __shfl_xor_sync(0xffffffffu, mh, 2));
            float sl = 0.f, shs = 0.f;
            #pragma unroll
            for (int nt = 0; nt < 7; nt++) {
                s[nt][0] = __expf(s[nt][0] - ml); sl  += s[nt][0];
                s[nt][1] = __expf(s[nt][1] - ml); sl  += s[nt][1];
                s[nt][2] = __expf(s[nt][2] - mh); shs += s[nt][2];
                s[nt][3] = __expf(s[nt][3] - mh); shs += s[nt][3];
            }
            sl  += __shfl_xor_sync(0xffffffffu, sl, 1);
            sl  += __shfl_xor_sync(0xffffffffu, sl, 2);
            shs += __shfl_xor_sync(0xffffffffu, shs, 1);
            shs += __shfl_xor_sync(0xffffffffu, shs, 2);
            const float il = 1.f / sl, ih = 1.f / shs;

            // P accum -> A fragments (accum layout of tile pair == A layout)
            uint32_t pa[4][4];
            #pragma unroll
            for (int kt = 0; kt < 4; kt++) {
                int n0 = 2 * kt, n1 = 2 * kt + 1;
                pa[kt][0] = f2h2(s[n0][0] * il, s[n0][1] * il);
                pa[kt][1] = f2h2(s[n0][2] * ih, s[n0][3] * ih);
                if (n1 < 7) {
                    pa[kt][2] = f2h2(s[n1][0] * il, s[n1][1] * il);
                    pa[kt][3] = f2h2(s[n1][2] * ih, s[n1][3] * ih);
                } else { pa[kt][2] = 0u; pa[kt][3] = 0u; }
            }

            // O = P @ V
            float o[4][4];
            #pragma unroll
            for (int d = 0; d < 4; d++) o[d][0]=o[d][1]=o[d][2]=o[d][3]=0.f;
            #pragma unroll
            for (int kt = 0; kt < 4; kt++) {
                MMA(o[0][0],o[0][1],o[0][2],o[0][3],
                    pa[kt][0],pa[kt][1],pa[kt][2],pa[kt][3], vb[kt][0], vb[kt][1]);
                MMA(o[1][0],o[1][1],o[1][2],o[1][3],
                    pa[kt][0],pa[kt][1],pa[kt][2],pa[kt][3], vb[kt][2], vb[kt][3]);
                MMA(o[2][0],o[2][1],o[2][2],o[2][3],
                    pa[kt][0],pa[kt][1],pa[kt][2],pa[kt][3], vb[kt][4], vb[kt][5]);
                MMA(o[3][0],o[3][1],o[3][2],o[3][3],
                    pa[kt][0],pa[kt][1],pa[kt][2],pa[kt][3], vb[kt][6], vb[kt][7]);
            }
            const int orow = rbase + m * 16 + (lane >> 2);
            #pragma unroll
            for (int d = 0; d < 4; d++) {
                int col = h * 32 + d * 8 + ((lane & 3) << 1);
                *reinterpret_cast<__half2*>(xh + orow * XH_P + col) =
                    __floats2half2_rn(o[d][0], o[d][1]);
                *reinterpret_cast<__half2*>(xh + (orow + 8) * XH_P + col) =
                    __floats2half2_rn(o[d][2], o[d][3]);
            }
        }
    }
    __syncthreads();

    // ================= Phase 3: out = attn_out @ Wmerge + bmerge =============
    {
        uint32_t af2[8][4];
        uint32_t a0 = xh_s + (((warp << 4) + (lane & 15)) * XH_P + ((lane >> 4) << 3)) * 2;
        #pragma unroll
        for (int kk = 0; kk < 8; kk++)
            LDSM4(af2[kk][0], af2[kk][1], af2[kk][2], af2[kk][3], a0 + kk * 32);

        const int vw = warp >> 2;
        const int ilocal = ((warp & 3) << 4) + (lane >> 2);
        float* obase = out + (size_t)(blockIdx.x * 2 + vw) * (PW * DD);

        for (int cn = 0; cn < 2; cn++) {
            __syncthreads();
            #pragma unroll
            for (int i2 = tid; i2 < 2048; i2 += 256) {
                int r = i2 >> 4, c4 = (i2 & 15) << 2;
                *reinterpret_cast<uint2*>(wbuf + r * WB_P + c4) =
                    *reinterpret_cast<const uint2*>(g_wmerge + r * 128 + cn * 64 + c4);
            }
            __syncthreads();

            float acc[8][4];
            #pragma unroll
            for (int nt = 0; nt < 8; nt++) {
                int col = cn * 64 + nt * 8 + ((lane & 3) << 1);
                acc[nt][0] = __ldg(bmerge + col);
                acc[nt][1] = __ldg(bmerge + col + 1);
                acc[nt][2] = acc[nt][0];
                acc[nt][3] = acc[nt][1];
            }
            uint32_t wb0 = wb_s + ((lane & 15) * WB_P + ((lane >> 4) << 3)) * 2;
            #pragma unroll
            for (int kk = 0; kk < 8; kk++) {
                uint32_t b[4][4];
                #pragma unroll
                for (int np = 0; np < 4; np++)
                    LDSM4T(b[np][0], b[np][1], b[np][2], b[np][3],
                           wb0 + (kk * 16 * WB_P + np * 16) * 2);
                #pragma unroll
                for (int np = 0; np < 4; np++) {
                    MMA(acc[2*np][0],acc[2*np][1],acc[2*np][2],acc[2*np][3],
                        af2[kk][0],af2[kk][1],af2[kk][2],af2[kk][3], b[np][0], b[np][1]);
                    MMA(acc[2*np+1][0],acc[2*np+1][1],acc[2*np+1][2],acc[2*np+1][3],
                        af2[kk][0],af2[kk][1],af2[kk][2],af2[kk][3], b[np][2], b[np][3]);
                }
            }
            #pragma unroll
            for (int nt = 0; nt < 8; nt++) {
                int col = cn * 64 + nt * 8 + ((lane & 3) << 1);
                if (ilocal < PW)
                    *reinterpret_cast<float2*>(obase + ilocal * DD + col) =
                        make_float2(acc[nt][0], acc[nt][1]);
                if (ilocal + 8 < PW)
                    *reinterpret_cast<float2*>(obase + (ilocal + 8) * DD + col) =
                        make_float2(acc[nt][2], acc[nt][3]);
            }
        }
    }
}

extern "C" void kernel_launch(void* const* d_in, const int* in_sizes, int n_in,
                              void* d_out, int out_size)
{
    const float* x      = (const float*)d_in[0];
    const float* Wqkv   = (const float*)d_in[1];
    const float* bqkv   = (const float*)d_in[2];
    const float* Wmerge = (const float*)d_in[3];
    const float* bmerge = (const float*)d_in[4];
    const float* table  = (const float*)d_in[5];
    float* out = (float*)d_out;

    convert_w_kernel<<<192, 256>>>(Wqkv, Wmerge);

    const int nwin = in_sizes[0] / (PW * DD);   // 16384
    const int nblk = nwin / 2;                  // 8192

    cudaFuncSetAttribute(rpmha_mma_kernel,
                         cudaFuncAttributeMaxDynamicSharedMemorySize, SMEM_BYTES);
    rpmha_mma_kernel<<<nblk, 256, SMEM_BYTES>>>(x, bqkv, bmerge, table, out);
}

// round 4
// speedup vs baseline: 7.8191x; 1.0601x over previous
#include <cuda_runtime.h>
#include <cuda_fp16.h>
#include <cstdint>
#include <math.h>

#define PW 49        // tokens per window
#define DD 128       // feature dim

// fp16 weight caches (converted once per launch by a prep kernel)
__device__ __half g_wqkv[128 * 384];
__device__ __half g_wmerge[128 * 128];

__global__ void convert_w_kernel(const float* __restrict__ wq,
                                 const float* __restrict__ wm)
{
    int i = blockIdx.x * 256 + threadIdx.x;
    if (i < 128 * 384) g_wqkv[i]   = __float2half_rn(wq[i]);
    if (i < 128 * 128) g_wmerge[i] = __float2half_rn(wm[i]);
}

// ---------------- smem layout (in halfs), 1 window per CTA ----------------
// xh   : [64][136]   x input (rows 49..63 zeroed); reused as attn-out buffer
// qkv  : [64][392]   fp16 qkv (q pre-scaled)
// wbuf : 2 x [128][72] double-buffered weight chunk staging (64 cols/chunk)
// tb   : 676 fp32    relative-position bias table
static constexpr int XH_P   = 136;
static constexpr int QKV_P  = 392;
static constexpr int WB_P   = 72;
static constexpr int WB_STAGE = 128 * WB_P;            // 9216 halfs
static constexpr int XH_OFF  = 0;
static constexpr int QKV_OFF = 64 * XH_P;              // 8704
static constexpr int WB_OFF  = QKV_OFF + 64 * QKV_P;   // 33792
static constexpr int HALFS   = WB_OFF + 2 * WB_STAGE;  // 52224
static constexpr int SMEM_BYTES = HALFS * 2 + 676 * 4; // 107152 -> 2 CTAs/SM

__device__ __forceinline__ uint32_t cvta_s(const void* p)
{
    return (uint32_t)__cvta_generic_to_shared(p);
}
__device__ __forceinline__ uint32_t f2h2(float a, float b)
{
    __half2 h = __floats2half2_rn(a, b);
    return *reinterpret_cast<uint32_t*>(&h);
}

#define LDSM4(R0,R1,R2,R3,ADDR) \
    asm volatile("ldmatrix.sync.aligned.m8n8.x4.shared.b16 {%0,%1,%2,%3},[%4];" \
        : "=r"(R0),"=r"(R1),"=r"(R2),"=r"(R3) : "r"(ADDR))
#define LDSM4T(R0,R1,R2,R3,ADDR) \
    asm volatile("ldmatrix.sync.aligned.m8n8.x4.trans.shared.b16 {%0,%1,%2,%3},[%4];" \
        : "=r"(R0),"=r"(R1),"=r"(R2),"=r"(R3) : "r"(ADDR))
#define MMA(C0,C1,C2,C3,A0,A1,A2,A3,B0,B1) \
    asm volatile("mma.sync.aligned.m16n8k16.row.col.f32.f16.f16.f32 " \
        "{%0,%1,%2,%3},{%4,%5,%6,%7},{%8,%9},{%0,%1,%2,%3};" \
        : "+f"(C0),"+f"(C1),"+f"(C2),"+f"(C3) \
        : "r"(A0),"r"(A1),"r"(A2),"r"(A3),"r"(B0),"r"(B1))
#define CP_COMMIT() asm volatile("cp.async.commit_group;")
#define CP_WAIT(N)  asm volatile("cp.async.wait_group %0;"::"n"(N))

// Stage one 128x64 fp16 weight chunk into wbuf[(chunk&1)] via cp.async.
// chunks 0..5 = Wqkv col-chunks, chunks 6..7 = Wmerge col-chunks.
__device__ __forceinline__ void stage_chunk(int chunk, __half* wbuf, int tid)
{
    __half* dst = wbuf + (chunk & 1) * WB_STAGE;
    const __half* src; int pitch, col0;
    if (chunk < 6) { src = g_wqkv;   pitch = 384; col0 = chunk * 64; }
    else           { src = g_wmerge; pitch = 128; col0 = (chunk - 6) * 64; }
    #pragma unroll
    for (int t = 0; t < 8; t++) {
        int idx = tid + t * 128;
        int r = idx >> 3, cs = (idx & 7) << 3;
        uint32_t d = cvta_s(dst + r * WB_P + cs);
        asm volatile("cp.async.cg.shared.global [%0],[%1],16;"
                     :: "r"(d), "l"(src + r * pitch + col0 + cs));
    }
    CP_COMMIT();
}

__global__ void __launch_bounds__(128, 2)
rpmha_mma_kernel(const float* __restrict__ x,
                 const float* __restrict__ bqkv,
                 const float* __restrict__ bmerge,
                 const float* __restrict__ table,
                 float* __restrict__ out)
{
    extern __shared__ __half sh[];
    __half* xh   = sh + XH_OFF;
    __half* qkv  = sh + QKV_OFF;
    __half* wbuf = sh + WB_OFF;
    float*  tb   = reinterpret_cast<float*>(sh + HALFS);

    const int tid = threadIdx.x, warp = tid >> 5, lane = tid & 31;

    // kick off weight pipeline before touching x (overlap)
    stage_chunk(0, wbuf, tid);
    stage_chunk(1, wbuf, tid);

    // ---- load 1 window of x -> fp16 smem (pad rows zeroed) + bias table ----
    const float* xg = x + (size_t)blockIdx.x * (PW * DD);
    #pragma unroll 4
    for (int idx = tid; idx < 2048; idx += 128) {
        int row = idx >> 5, c4 = (idx & 31) << 2;
        uint2 st;
        if (row < PW) {
            float4 f = *reinterpret_cast<const float4*>(xg + row * DD + c4);
            st.x = f2h2(f.x, f.y); st.y = f2h2(f.z, f.w);
        } else { st.x = 0u; st.y = 0u; }
        *reinterpret_cast<uint2*>(xh + row * XH_P + c4) = st;
    }
    for (int i = tid; i < 676; i += 128) tb[i] = table[i];
    __syncthreads();

    const uint32_t xh_s  = cvta_s(xh);
    const uint32_t qkv_s = cvta_s(qkv);
    const float scale = 0.17677669529663687f;  // 1/sqrt(32)

    // ---- persistent A fragments: x rows [16*warp, 16*warp+16), K=128 ----
    uint32_t af[8][4];
    {
        uint32_t a0 = xh_s + (((warp << 4) + (lane & 15)) * XH_P + ((lane >> 4) << 3)) * 2;
        #pragma unroll
        for (int kk = 0; kk < 8; kk++)
            LDSM4(af[kk][0], af[kk][1], af[kk][2], af[kk][3], a0 + kk * 32);
    }

    // ================= Phase 1: qkv = x @ Wqkv + bqkv =================
    for (int cn = 0; cn < 6; cn++) {
        CP_WAIT(1);            // chunk cn resident
        __syncthreads();

        float acc[8][4];
        #pragma unroll
        for (int nt = 0; nt < 8; nt++) {
            int col = cn * 64 + nt * 8 + ((lane & 3) << 1);
            acc[nt][0] = __ldg(bqkv + col);
            acc[nt][1] = __ldg(bqkv + col + 1);
            acc[nt][2] = acc[nt][0];
            acc[nt][3] = acc[nt][1];
        }
        uint32_t wb0 = cvta_s(wbuf + (cn & 1) * WB_STAGE)
                     + ((lane & 15) * WB_P + ((lane >> 4) << 3)) * 2;
        #pragma unroll
        for (int kk = 0; kk < 8; kk++) {
            uint32_t b[4][4];
            #pragma unroll
            for (int np = 0; np < 4; np++)
                LDSM4T(b[np][0], b[np][1], b[np][2], b[np][3],
                       wb0 + (kk * 16 * WB_P + np * 16) * 2);
            #pragma unroll
            for (int np = 0; np < 4; np++) {
                MMA(acc[2*np][0],acc[2*np][1],acc[2*np][2],acc[2*np][3],
                    af[kk][0],af[kk][1],af[kk][2],af[kk][3], b[np][0], b[np][1]);
                MMA(acc[2*np+1][0],acc[2*np+1][1],acc[2*np+1][2],acc[2*np+1][3],
                    af[kk][0],af[kk][1],af[kk][2],af[kk][3], b[np][2], b[np][3]);
            }
        }
        const float mul = (cn < 2) ? scale : 1.0f;  // q cols < 128 pre-scaled
        const int row = (warp << 4) + (lane >> 2);
        #pragma unroll
        for (int nt = 0; nt < 8; nt++) {
            int col = cn * 64 + nt * 8 + ((lane & 3) << 1);
            *reinterpret_cast<__half2*>(qkv + row * QKV_P + col) =
                __floats2half2_rn(acc[nt][0] * mul, acc[nt][1] * mul);
            *reinterpret_cast<__half2*>(qkv + (row + 8) * QKV_P + col) =
                __floats2half2_rn(acc[nt][2] * mul, acc[nt][3] * mul);
        }
        __syncthreads();       // all warps done reading wbuf[cn&1]
        if (cn + 2 < 8) stage_chunk(cn + 2, wbuf, tid);  // merge chunks load during phase 2
    }

    // ================= Phase 2: attention, warp = head =================
    {
        const int h = warp;

        // K as B fragments: 7 n-tiles (tokens) x 2 k-steps (d)
        uint32_t kb[7][4];
        #pragma unroll
        for (int nt = 0; nt < 7; nt++) {
            uint32_t addr = qkv_s + ((nt * 8 + (lane & 7)) * QKV_P
                                     + 128 + h * 32 + ((lane >> 3) << 3)) * 2;
            LDSM4(kb[nt][0], kb[nt][1], kb[nt][2], kb[nt][3], addr);
        }
        // V as B fragments: 4 k-steps (tokens) x 4 n-tiles (d)
        uint32_t vb[4][8];
        #pragma unroll
        for (int kt = 0; kt < 4; kt++)
            #pragma unroll
            for (int dp = 0; dp < 2; dp++) {
                uint32_t addr = qkv_s + ((kt * 16 + (lane & 15)) * QKV_P
                                         + 256 + h * 32 + dp * 16 + ((lane >> 4) << 3)) * 2;
                LDSM4T(vb[kt][dp*4+0], vb[kt][dp*4+1], vb[kt][dp*4+2], vb[kt][dp*4+3], addr);
            }

        #pragma unroll
        for (int m = 0; m < 4; m++) {
            uint32_t qa[4], qa2[4];
            uint32_t qaddr = qkv_s + ((m * 16 + (lane & 15)) * QKV_P
                                      + h * 32 + ((lane >> 4) << 3)) * 2;
            LDSM4(qa[0], qa[1], qa[2], qa[3], qaddr);
            LDSM4(qa2[0], qa2[1], qa2[2], qa2[3], qaddr + 32);

            float s[7][4];
            #pragma unroll
            for (int nt = 0; nt < 7; nt++) {
                s[nt][0] = s[nt][1] = s[nt][2] = s[nt][3] = 0.f;
                MMA(s[nt][0],s[nt][1],s[nt][2],s[nt][3],
                    qa[0],qa[1],qa[2],qa[3], kb[nt][0], kb[nt][1]);
                MMA(s[nt][0],s[nt][1],s[nt][2],s[nt][3],
                    qa2[0],qa2[1],qa2[2],qa2[3], kb[nt][2], kb[nt][3]);
            }

            // relative position bias + j-mask
            int i0 = m * 16 + (lane >> 2), i1 = i0 + 8;
            int i0c = (i0 < PW) ? i0 : 0, i1c = (i1 < PW) ? i1 : 0;
            int r0 = (i0c * 147) >> 10, c0i = i0c - r0 * 7;
            int r1 = (i1c * 147) >> 10, c1i = i1c - r1 * 7;
            #pragma unroll
            for (int nt = 0; nt < 7; nt++) {
                #pragma unroll
                for (int e = 0; e < 2; e++) {
                    int j = nt * 8 + ((lane & 3) << 1) + e;
                    if (j < PW) {
                        int rj = (j * 147) >> 10, cj = j - rj * 7;
                        s[nt][e]   += tb[(((r0 - rj + 6) * 13) + (c0i - cj + 6)) * 4 + h];
                        s[nt][2+e] += tb[(((r1 - rj + 6) * 13) + (c1i - cj + 6)) * 4 + h];
                    } else {
                        s[nt][e] = -1e30f; s[nt][2+e] = -1e30f;
                    }
                }
            }

            // softmax: rows i0 (elems 0,1) / i1 (elems 2,3), quad shfl reduce
            float ml = -1e30f, mh = -1e30f;
            #pragma unroll
            for (int nt = 0; nt < 7; nt++) {
                ml = fmaxf(ml, fmaxf(s[nt][0], s[nt][1]));
                mh = fmaxf(mh, fmaxf(s[nt][2], s[nt][3]));
            }
            ml = fmaxf(ml, __shfl_xor_sync(0xffffffffu, ml, 1));
            ml = fmaxf(ml, __shfl_xor_sync(0xffffffffu, ml, 2));
            mh = fmaxf(mh, __shfl_xor_sync(0xffffffffu, mh, 1));
            mh = fmaxf(mh, __shfl_xor_sync(0xffffffffu, mh, 2));
            float sl = 0.f, shs = 0.f;
            #pragma unroll
            for (int nt = 0; nt < 7; nt++) {
                s[nt][0] = __expf(s[nt][0] - ml); sl  += s[nt][0];
                s[nt][1] = __expf(s[nt][1] - ml); sl  += s[nt][1];
                s[nt][2] = __expf(s[nt][2] - mh); shs += s[nt][2];
                s[nt][3] = __expf(s[nt][3] - mh); shs += s[nt][3];
            }
            sl  += __shfl_xor_sync(0xffffffffu, sl, 1);
            sl  += __shfl_xor_sync(0xffffffffu, sl, 2);
            shs += __shfl_xor_sync(0xffffffffu, shs, 1);
            shs += __shfl_xor_sync(0xffffffffu, shs, 2);
            const float il = 1.f / sl, ih = 1.f / shs;

            // P accum -> A fragments
            uint32_t pa[4][4];
            #pragma unroll
            for (int kt = 0; kt < 4; kt++) {
                int n0 = 2 * kt, n1 = 2 * kt + 1;
                pa[kt][0] = f2h2(s[n0][0] * il, s[n0][1] * il);
                pa[kt][1] = f2h2(s[n0][2] * ih, s[n0][3] * ih);
                if (n1 < 7) {
                    pa[kt][2] = f2h2(s[n1][0] * il, s[n1][1] * il);
                    pa[kt][3] = f2h2(s[n1][2] * ih, s[n1][3] * ih);
                } else { pa[kt][2] = 0u; pa[kt][3] = 0u; }
            }

            // O = P @ V
            float o[4][4];
            #pragma unroll
            for (int d = 0; d < 4; d++) o[d][0]=o[d][1]=o[d][2]=o[d][3]=0.f;
            #pragma unroll
            for (int kt = 0; kt < 4; kt++) {
                MMA(o[0][0],o[0][1],o[0][2],o[0][3],
                    pa[kt][0],pa[kt][1],pa[kt][2],pa[kt][3], vb[kt][0], vb[kt][1]);
                MMA(o[1][0],o[1][1],o[1][2],o[1][3],
                    pa[kt][0],pa[kt][1],pa[kt][2],pa[kt][3], vb[kt][2], vb[kt][3]);
                MMA(o[2][0],o[2][1],o[2][2],o[2][3],
                    pa[kt][0],pa[kt][1],pa[kt][2],pa[kt][3], vb[kt][4], vb[kt][5]);
                MMA(o[3][0],o[3][1],o[3][2],o[3][3],
                    pa[kt][0],pa[kt][1],pa[kt][2],pa[kt][3], vb[kt][6], vb[kt][7]);
            }
            const int orow = m * 16 + (lane >> 2);
            #pragma unroll
            for (int d = 0; d < 4; d++) {
                int col = h * 32 + d * 8 + ((lane & 3) << 1);
                *reinterpret_cast<__half2*>(xh + orow * XH_P + col) =
                    __floats2half2_rn(o[d][0], o[d][1]);
                *reinterpret_cast<__half2*>(xh + (orow + 8) * XH_P + col) =
                    __floats2half2_rn(o[d][2], o[d][3]);
            }
        }
    }
    __syncthreads();

    // ================= Phase 3: out = attn_out @ Wmerge + bmerge =============
    {
        uint32_t af2[8][4];
        uint32_t a0 = xh_s + (((warp << 4) + (lane & 15)) * XH_P + ((lane >> 4) << 3)) * 2;
        #pragma unroll
        for (int kk = 0; kk < 8; kk++)
            LDSM4(af2[kk][0], af2[kk][1], af2[kk][2], af2[kk][3], a0 + kk * 32);

        const int ilocal = (warp << 4) + (lane >> 2);
        float* obase = out + (size_t)blockIdx.x * (PW * DD);

        #pragma unroll
        for (int cn = 0; cn < 2; cn++) {
            if (cn == 0) { CP_WAIT(1); } else { CP_WAIT(0); }
            __syncthreads();

            float acc[8][4];
            #pragma unroll
            for (int nt = 0; nt < 8; nt++) {
                int col = cn * 64 + nt * 8 + ((lane & 3) << 1);
                acc[nt][0] = __ldg(bmerge + col);
                acc[nt][1] = __ldg(bmerge + col + 1);
                acc[nt][2] = acc[nt][0];
                acc[nt][3] = acc[nt][1];
            }
            uint32_t wb0 = cvta_s(wbuf + (cn & 1) * WB_STAGE)
                         + ((lane & 15) * WB_P + ((lane >> 4) << 3)) * 2;
            #pragma unroll
            for (int kk = 0; kk < 8; kk++) {
                uint32_t b[4][4];
                #pragma unroll
                for (int np = 0; np < 4; np++)
                    LDSM4T(b[np][0], b[np][1], b[np][2], b[np][3],
                           wb0 + (kk * 16 * WB_P + np * 16) * 2);
                #pragma unroll
                for (int np = 0; np < 4; np++) {
                    MMA(acc[2*np][0],acc[2*np][1],acc[2*np][2],acc[2*np][3],
                        af2[kk][0],af2[kk][1],af2[kk][2],af2[kk][3], b[np][0], b[np][1]);
                    MMA(acc[2*np+1][0],acc[2*np+1][1],acc[2*np+1][2],acc[2*np+1][3],
                        af2[kk][0],af2[kk][1],af2[kk][2],af2[kk][3], b[np][2], b[np][3]);
                }
            }
            #pragma unroll
            for (int nt = 0; nt < 8; nt++) {
                int col = cn * 64 + nt * 8 + ((lane & 3) << 1);
                if (ilocal < PW)
                    *reinterpret_cast<float2*>(obase + ilocal * DD + col) =
                        make_float2(acc[nt][0], acc[nt][1]);
                if (ilocal + 8 < PW)
                    *reinterpret_cast<float2*>(obase + (ilocal + 8) * DD + col) =
                        make_float2(acc[nt][2], acc[nt][3]);
            }
        }
    }
}

extern "C" void kernel_launch(void* const* d_in, const int* in_sizes, int n_in,
                              void* d_out, int out_size)
{
    const float* x      = (const float*)d_in[0];
    const float* Wqkv   = (const float*)d_in[1];
    const float* bqkv   = (const float*)d_in[2];
    const float* Wmerge = (const float*)d_in[3];
    const float* bmerge = (const float*)d_in[4];
    const float* table  = (const float*)d_in[5];
    float* out = (float*)d_out;

    convert_w_kernel<<<192, 256>>>(Wqkv, Wmerge);

    const int nwin = in_sizes[0] / (PW * DD);   // 16384

    cudaFuncSetAttribute(rpmha_mma_kernel,
                         cudaFuncAttributeMaxDynamicSharedMemorySize, SMEM_BYTES);
    rpmha_mma_kernel<<<nwin, 128, SMEM_BYTES>>>(x, bqkv, bmerge, table, out);
}

// round 5
// speedup vs baseline: 9.5715x; 1.2241x over previous
#include <cuda_runtime.h>
#include <cuda_fp16.h>
#include <cstdint>
#include <math.h>

#define PW 49        // tokens per window
#define DD 128       // feature dim

// fp16 weight caches (converted once per launch by a prep kernel)
__device__ __half g_wqkv[128 * 384];
__device__ __half g_wmerge[128 * 128];

__global__ void convert_w_kernel(const float* __restrict__ wq,
                                 const float* __restrict__ wm)
{
    int i = blockIdx.x * 256 + threadIdx.x;
    if (i < 128 * 384) g_wqkv[i]   = __float2half_rn(wq[i]);
    if (i < 128 * 128) g_wmerge[i] = __float2half_rn(wm[i]);
}

// ---------------- smem layout (in halfs), 1 window per CTA ----------------
// qkv  : [64][392]  fp16 qkv. v-region (cols 256..383) doubles as x staging;
//                   q-region (cols 0..127) doubles as attn-out buffer.
// wbuf : 2 x [128][40] double-buffered 32-col weight chunk staging
// tb   : 676 fp32   relative-position bias table
static constexpr int QKV_P    = 392;
static constexpr int WB_P     = 40;
static constexpr int WB_STAGE = 128 * WB_P;              // 5120 halfs
static constexpr int QKV_OFF  = 0;
static constexpr int WB_OFF   = 64 * QKV_P;              // 25088
static constexpr int HALFS    = WB_OFF + 2 * WB_STAGE;   // 35328
static constexpr int SMEM_BYTES = HALFS * 2 + 676 * 4;   // 73360 -> 3 CTAs/SM

__device__ __forceinline__ uint32_t cvta_s(const void* p)
{
    return (uint32_t)__cvta_generic_to_shared(p);
}
__device__ __forceinline__ uint32_t f2h2(float a, float b)
{
    __half2 h = __floats2half2_rn(a, b);
    return *reinterpret_cast<uint32_t*>(&h);
}

#define LDSM4(R0,R1,R2,R3,ADDR) \
    asm volatile("ldmatrix.sync.aligned.m8n8.x4.shared.b16 {%0,%1,%2,%3},[%4];" \
        : "=r"(R0),"=r"(R1),"=r"(R2),"=r"(R3) : "r"(ADDR))
#define LDSM4T(R0,R1,R2,R3,ADDR) \
    asm volatile("ldmatrix.sync.aligned.m8n8.x4.trans.shared.b16 {%0,%1,%2,%3},[%4];" \
        : "=r"(R0),"=r"(R1),"=r"(R2),"=r"(R3) : "r"(ADDR))
#define MMA(C0,C1,C2,C3,A0,A1,A2,A3,B0,B1) \
    asm volatile("mma.sync.aligned.m16n8k16.row.col.f32.f16.f16.f32 " \
        "{%0,%1,%2,%3},{%4,%5,%6,%7},{%8,%9},{%0,%1,%2,%3};" \
        : "+f"(C0),"+f"(C1),"+f"(C2),"+f"(C3) \
        : "r"(A0),"r"(A1),"r"(A2),"r"(A3),"r"(B0),"r"(B1))
#define CP_COMMIT() asm volatile("cp.async.commit_group;")
#define CP_WAIT(N)  asm volatile("cp.async.wait_group %0;"::"n"(N))

// Stage one 128x32 fp16 weight chunk into wbuf slot (chunk&1) via cp.async.
// chunks 0..11 = Wqkv 32-col chunks, chunks 12..15 = Wmerge 32-col chunks.
__device__ __forceinline__ void stage_chunk(int chunk, __half* wbuf, int tid)
{
    __half* dst = wbuf + (chunk & 1) * WB_STAGE;
    const __half* src; int pitch, col0;
    if (chunk < 12) { src = g_wqkv;   pitch = 384; col0 = chunk * 32; }
    else            { src = g_wmerge; pitch = 128; col0 = (chunk - 12) * 32; }
    #pragma unroll
    for (int t = 0; t < 4; t++) {
        int idx = tid + t * 128;
        int r = idx >> 2, cs = (idx & 3) << 3;
        uint32_t d = cvta_s(dst + r * WB_P + cs);
        asm volatile("cp.async.cg.shared.global [%0],[%1],16;"
                     :: "r"(d), "l"(src + r * pitch + col0 + cs));
    }
    CP_COMMIT();
}

__global__ void __launch_bounds__(128, 3)
rpmha_mma_kernel(const float* __restrict__ x,
                 const float* __restrict__ bqkv,
                 const float* __restrict__ bmerge,
                 const float* __restrict__ table,
                 float* __restrict__ out)
{
    extern __shared__ __half sh[];
    __half* qkv  = sh + QKV_OFF;
    __half* wbuf = sh + WB_OFF;
    float*  tb   = reinterpret_cast<float*>(sh + HALFS);

    const int tid = threadIdx.x, warp = tid >> 5, lane = tid & 31;

    // kick off weight pipeline before touching x (overlap)
    stage_chunk(0, wbuf, tid);
    stage_chunk(1, wbuf, tid);

    // ---- stage x (fp32->fp16) into qkv v-region (cols 256..383), pad rows 0 ----
    const float* xg = x + (size_t)blockIdx.x * (PW * DD);
    #pragma unroll 4
    for (int idx = tid; idx < 2048; idx += 128) {
        int row = idx >> 5, c4 = (idx & 31) << 2;
        uint2 st;
        if (row < PW) {
            float4 f = *reinterpret_cast<const float4*>(xg + row * DD + c4);
            st.x = f2h2(f.x, f.y); st.y = f2h2(f.z, f.w);
        } else { st.x = 0u; st.y = 0u; }
        *reinterpret_cast<uint2*>(qkv + row * QKV_P + 256 + c4) = st;
    }
    for (int i = tid; i < 676; i += 128) tb[i] = table[i];
    __syncthreads();

    const uint32_t qkv_s = cvta_s(qkv);
    const float scale = 0.17677669529663687f;  // 1/sqrt(32)

    // ---- persistent A fragments: x rows [16*warp,16*warp+16), K=128 (v-region) ----
    uint32_t af[8][4];
    {
        uint32_t a0 = qkv_s + (((warp << 4) + (lane & 15)) * QKV_P
                               + 256 + ((lane >> 4) << 3)) * 2;
        #pragma unroll
        for (int kk = 0; kk < 8; kk++)
            LDSM4(af[kk][0], af[kk][1], af[kk][2], af[kk][3], a0 + kk * 32);
    }

    // ================= Phase 1: qkv = x @ Wqkv + bqkv (12 x 32-col chunks) ====
    for (int cn = 0; cn < 12; cn++) {
        CP_WAIT(1);            // chunk cn resident
        __syncthreads();

        float acc[4][4];
        #pragma unroll
        for (int nt = 0; nt < 4; nt++) {
            int col = cn * 32 + nt * 8 + ((lane & 3) << 1);
            acc[nt][0] = __ldg(bqkv + col);
            acc[nt][1] = __ldg(bqkv + col + 1);
            acc[nt][2] = acc[nt][0];
            acc[nt][3] = acc[nt][1];
        }
        uint32_t wb0 = cvta_s(wbuf + (cn & 1) * WB_STAGE)
                     + ((lane & 15) * WB_P + ((lane >> 4) << 3)) * 2;
        #pragma unroll
        for (int kk = 0; kk < 8; kk++) {
            uint32_t b[2][4];
            #pragma unroll
            for (int np = 0; np < 2; np++)
                LDSM4T(b[np][0], b[np][1], b[np][2], b[np][3],
                       wb0 + (kk * 16 * WB_P + np * 16) * 2);
            #pragma unroll
            for (int np = 0; np < 2; np++) {
                MMA(acc[2*np][0],acc[2*np][1],acc[2*np][2],acc[2*np][3],
                    af[kk][0],af[kk][1],af[kk][2],af[kk][3], b[np][0], b[np][1]);
                MMA(acc[2*np+1][0],acc[2*np+1][1],acc[2*np+1][2],acc[2*np+1][3],
                    af[kk][0],af[kk][1],af[kk][2],af[kk][3], b[np][2], b[np][3]);
            }
        }
        const float mul = (cn < 4) ? scale : 1.0f;  // q cols < 128 pre-scaled
        const int row = (warp << 4) + (lane >> 2);
        #pragma unroll
        for (int nt = 0; nt < 4; nt++) {
            int col = cn * 32 + nt * 8 + ((lane & 3) << 1);
            *reinterpret_cast<__half2*>(qkv + row * QKV_P + col) =
                __floats2half2_rn(acc[nt][0] * mul, acc[nt][1] * mul);
            *reinterpret_cast<__half2*>(qkv + (row + 8) * QKV_P + col) =
                __floats2half2_rn(acc[nt][2] * mul, acc[nt][3] * mul);
        }
        __syncthreads();       // all warps done reading wbuf slot
        stage_chunk(cn + 2, wbuf, tid);   // cn=10,11 stage Wmerge chunks 12,13
    }

    // ================= Phase 2: attention, warp = head =================
    {
        const int h = warp;

        // K as B fragments: 7 n-tiles (tokens) x 2 k-steps (d)
        uint32_t kb[7][4];
        #pragma unroll
        for (int nt = 0; nt < 7; nt++) {
            uint32_t addr = qkv_s + ((nt * 8 + (lane & 7)) * QKV_P
                                     + 128 + h * 32 + ((lane >> 3) << 3)) * 2;
            LDSM4(kb[nt][0], kb[nt][1], kb[nt][2], kb[nt][3], addr);
        }
        // V as B fragments: 4 k-steps (tokens) x 4 n-tiles (d)
        uint32_t vb[4][8];
        #pragma unroll
        for (int kt = 0; kt < 4; kt++)
            #pragma unroll
            for (int dp = 0; dp < 2; dp++) {
                uint32_t addr = qkv_s + ((kt * 16 + (lane & 15)) * QKV_P
                                         + 256 + h * 32 + dp * 16 + ((lane >> 4) << 3)) * 2;
                LDSM4T(vb[kt][dp*4+0], vb[kt][dp*4+1], vb[kt][dp*4+2], vb[kt][dp*4+3], addr);
            }

        #pragma unroll
        for (int m = 0; m < 4; m++) {
            uint32_t qa[4], qa2[4];
            uint32_t qaddr = qkv_s + ((m * 16 + (lane & 15)) * QKV_P
                                      + h * 32 + ((lane >> 4) << 3)) * 2;
            LDSM4(qa[0], qa[1], qa[2], qa[3], qaddr);
            LDSM4(qa2[0], qa2[1], qa2[2], qa2[3], qaddr + 32);

            float s[7][4];
            #pragma unroll
            for (int nt = 0; nt < 7; nt++) {
                s[nt][0] = s[nt][1] = s[nt][2] = s[nt][3] = 0.f;
                MMA(s[nt][0],s[nt][1],s[nt][2],s[nt][3],
                    qa[0],qa[1],qa[2],qa[3], kb[nt][0], kb[nt][1]);
                MMA(s[nt][0],s[nt][1],s[nt][2],s[nt][3],
                    qa2[0],qa2[1],qa2[2],qa2[3], kb[nt][2], kb[nt][3]);
            }

            // relative position bias + j-mask
            int i0 = m * 16 + (lane >> 2), i1 = i0 + 8;
            int i0c = (i0 < PW) ? i0 : 0, i1c = (i1 < PW) ? i1 : 0;
            int r0 = (i0c * 147) >> 10, c0i = i0c - r0 * 7;
            int r1 = (i1c * 147) >> 10, c1i = i1c - r1 * 7;
            #pragma unroll
            for (int nt = 0; nt < 7; nt++) {
                #pragma unroll
                for (int e = 0; e < 2; e++) {
                    int j = nt * 8 + ((lane & 3) << 1) + e;
                    if (j < PW) {
                        int rj = (j * 147) >> 10, cj = j - rj * 7;
                        s[nt][e]   += tb[(((r0 - rj + 6) * 13) + (c0i - cj + 6)) * 4 + h];
                        s[nt][2+e] += tb[(((r1 - rj + 6) * 13) + (c1i - cj + 6)) * 4 + h];
                    } else {
                        s[nt][e] = -1e30f; s[nt][2+e] = -1e30f;
                    }
                }
            }

            // softmax: rows i0 (elems 0,1) / i1 (elems 2,3), quad shfl reduce
            float ml = -1e30f, mh = -1e30f;
            #pragma unroll
            for (int nt = 0; nt < 7; nt++) {
                ml = fmaxf(ml, fmaxf(s[nt][0], s[nt][1]));
                mh = fmaxf(mh, fmaxf(s[nt][2], s[nt][3]));
            }
            ml = fmaxf(ml, __shfl_xor_sync(0xffffffffu, ml, 1));
            ml = fmaxf(ml, __shfl_xor_sync(0xffffffffu, ml, 2));
            mh = fmaxf(mh, __shfl_xor_sync(0xffffffffu, mh, 1));
            mh = fmaxf(mh, __shfl_xor_sync(0xffffffffu, mh, 2));
            float sl = 0.f, shs = 0.f;
            #pragma unroll
            for (int nt = 0; nt < 7; nt++) {
                s[nt][0] = __expf(s[nt][0] - ml); sl  += s[nt][0];
                s[nt][1] = __expf(s[nt][1] - ml); sl  += s[nt][1];
                s[nt][2] = __expf(s[nt][2] - mh); shs += s[nt][2];
                s[nt][3] = __expf(s[nt][3] - mh); shs += s[nt][3];
            }
            sl  += __shfl_xor_sync(0xffffffffu, sl, 1);
            sl  += __shfl_xor_sync(0xffffffffu, sl, 2);
            shs += __shfl_xor_sync(0xffffffffu, shs, 1);
            shs += __shfl_xor_sync(0xffffffffu, shs, 2);
            const float il = 1.f / sl, ih = 1.f / shs;

            // P accum -> A fragments
            uint32_t pa[4][4];
            #pragma unroll
            for (int kt = 0; kt < 4; kt++) {
                int n0 = 2 * kt, n1 = 2 * kt + 1;
                pa[kt][0] = f2h2(s[n0][0] * il, s[n0][1] * il);
                pa[kt][1] = f2h2(s[n0][2] * ih, s[n0][3] * ih);
                if (n1 < 7) {
                    pa[kt][2] = f2h2(s[n1][0] * il, s[n1][1] * il);
                    pa[kt][3] = f2h2(s[n1][2] * ih, s[n1][3] * ih);
                } else { pa[kt][2] = 0u; pa[kt][3] = 0u; }
            }

            // O = P @ V
            float o[4][4];
            #pragma unroll
            for (int d = 0; d < 4; d++) o[d][0]=o[d][1]=o[d][2]=o[d][3]=0.f;
            #pragma unroll
            for (int kt = 0; kt < 4; kt++) {
                MMA(o[0][0],o[0][1],o[0][2],o[0][3],
                    pa[kt][0],pa[kt][1],pa[kt][2],pa[kt][3], vb[kt][0], vb[kt][1]);
                MMA(o[1][0],o[1][1],o[1][2],o[1][3],
                    pa[kt][0],pa[kt][1],pa[kt][2],pa[kt][3], vb[kt][2], vb[kt][3]);
                MMA(o[2][0],o[2][1],o[2][2],o[2][3],
                    pa[kt][0],pa[kt][1],pa[kt][2],pa[kt][3], vb[kt][4], vb[kt][5]);
                MMA(o[3][0],o[3][1],o[3][2],o[3][3],
                    pa[kt][0],pa[kt][1],pa[kt][2],pa[kt][3], vb[kt][6], vb[kt][7]);
            }
            // attn-out -> q region (warp=head owns cols 32h..32h+31 exclusively)
            const int orow = m * 16 + (lane >> 2);
            #pragma unroll
            for (int d = 0; d < 4; d++) {
                int col = h * 32 + d * 8 + ((lane & 3) << 1);
                *reinterpret_cast<__half2*>(qkv + orow * QKV_P + col) =
                    __floats2half2_rn(o[d][0], o[d][1]);
                *reinterpret_cast<__half2*>(qkv + (orow + 8) * QKV_P + col) =
                    __floats2half2_rn(o[d][2], o[d][3]);
            }
        }
    }
    __syncthreads();

    // ============ Phase 3: out = attn_out @ Wmerge + bmerge (4 chunks) =======
    {
        uint32_t af2[8][4];
        uint32_t a0 = qkv_s + (((warp << 4) + (lane & 15)) * QKV_P
                               + ((lane >> 4) << 3)) * 2;
        #pragma unroll
        for (int kk = 0; kk < 8; kk++)
            LDSM4(af2[kk][0], af2[kk][1], af2[kk][2], af2[kk][3], a0 + kk * 32);

        const int ilocal = (warp << 4) + (lane >> 2);
        float* obase = out + (size_t)blockIdx.x * (PW * DD);

        #pragma unroll
        for (int cm = 0; cm < 4; cm++) {
            if (cm < 3) { CP_WAIT(1); } else { CP_WAIT(0); }
            __syncthreads();

            float acc[4][4];
            #pragma unroll
            for (int nt = 0; nt < 4; nt++) {
                int col = cm * 32 + nt * 8 + ((lane & 3) << 1);
                acc[nt][0] = __ldg(bmerge + col);
                acc[nt][1] = __ldg(bmerge + col + 1);
                acc[nt][2] = acc[nt][0];
                acc[nt][3] = acc[nt][1];
            }
            uint32_t wb0 = cvta_s(wbuf + (cm & 1) * WB_STAGE)
                         + ((lane & 15) * WB_P + ((lane >> 4) << 3)) * 2;
            #pragma unroll
            for (int kk = 0; kk < 8; kk++) {
                uint32_t b[2][4];
                #pragma unroll
                for (int np = 0; np < 2; np++)
                    LDSM4T(b[np][0], b[np][1], b[np][2], b[np][3],
                           wb0 + (kk * 16 * WB_P + np * 16) * 2);
                #pragma unroll
                for (int np = 0; np < 2; np++) {
                    MMA(acc[2*np][0],acc[2*np][1],acc[2*np][2],acc[2*np][3],
                        af2[kk][0],af2[kk][1],af2[kk][2],af2[kk][3], b[np][0], b[np][1]);
                    MMA(acc[2*np+1][0],acc[2*np+1][1],acc[2*np+1][2],acc[2*np+1][3],
                        af2[kk][0],af2[kk][1],af2[kk][2],af2[kk][3], b[np][2], b[np][3]);
                }
            }
            #pragma unroll
            for (int nt = 0; nt < 4; nt++) {
                int col = cm * 32 + nt * 8 + ((lane & 3) << 1);
                if (ilocal < PW)
                    *reinterpret_cast<float2*>(obase + ilocal * DD + col) =
                        make_float2(acc[nt][0], acc[nt][1]);
                if (ilocal + 8 < PW)
                    *reinterpret_cast<float2*>(obase + (ilocal + 8) * DD + col) =
                        make_float2(acc[nt][2], acc[nt][3]);
            }
            if (cm < 2) {
                __syncthreads();               // slot consumers done
                stage_chunk(cm + 14, wbuf, tid);
            }
        }
    }
}

extern "C" void kernel_launch(void* const* d_in, const int* in_sizes, int n_in,
                              void* d_out, int out_size)
{
    const float* x      = (const float*)d_in[0];
    const float* Wqkv   = (const float*)d_in[1];
    const float* bqkv   = (const float*)d_in[2];
    const float* Wmerge = (const float*)d_in[3];
    const float* bmerge = (const float*)d_in[4];
    const float* table  = (const float*)d_in[5];
    float* out = (float*)d_out;

    convert_w_kernel<<<192, 256>>>(Wqkv, Wmerge);

    const int nwin = in_sizes[0] / (PW * DD);   // 16384

    cudaFuncSetAttribute(rpmha_mma_kernel,
                         cudaFuncAttributeMaxDynamicSharedMemorySize, SMEM_BYTES);
    rpmha_mma_kernel<<<nwin, 128, SMEM_BYTES>>>(x, bqkv, bmerge, table, out);
}

// round 7
// speedup vs baseline: 10.2131x; 1.0670x over previous
#include <cuda_runtime.h>
#include <cuda_fp16.h>
#include <cstdint>
#include <math.h>

#define PW 49        // tokens per window
#define DD 128       // feature dim

// fp16 weight caches (converted once per launch by a prep kernel)
__device__ __half g_wqkv[128 * 384];
__device__ __half g_wmerge[128 * 128];

__global__ void convert_w_kernel(const float* __restrict__ wq,
                                 const float* __restrict__ wm)
{
    int i = blockIdx.x * 256 + threadIdx.x;
    if (i < 128 * 384) g_wqkv[i]   = __float2half_rn(wq[i]);
    if (i < 128 * 128) g_wmerge[i] = __float2half_rn(wm[i]);
}

// ---------------- smem layout (in halfs), 1 window per CTA ----------------
// qkv  : [64][392]  fp16 qkv. v-region (cols 256..383) doubles as x staging;
//                   q-region (cols 0..127) doubles as attn-out buffer.
// wbuf : 2 x [128][40] double-buffered 32-col weight chunk staging
// tb   : 676 fp32   relative-position bias table
static constexpr int QKV_P    = 392;
static constexpr int WB_P     = 40;
static constexpr int WB_STAGE = 128 * WB_P;              // 5120 halfs
static constexpr int QKV_OFF  = 0;
static constexpr int WB_OFF   = 64 * QKV_P;              // 25088
static constexpr int HALFS    = WB_OFF + 2 * WB_STAGE;   // 35328
static constexpr int SMEM_BYTES = HALFS * 2 + 676 * 4;   // 73360 -> 3 CTAs/SM

__device__ __forceinline__ uint32_t cvta_s(const void* p)
{
    return (uint32_t)__cvta_generic_to_shared(p);
}
__device__ __forceinline__ uint32_t f2h2(float a, float b)
{
    __half2 h = __floats2half2_rn(a, b);
    return *reinterpret_cast<uint32_t*>(&h);
}

#define LDSM4(R0,R1,R2,R3,ADDR) \
    asm volatile("ldmatrix.sync.aligned.m8n8.x4.shared.b16 {%0,%1,%2,%3},[%4];" \
        : "=r"(R0),"=r"(R1),"=r"(R2),"=r"(R3) : "r"(ADDR))
#define LDSM4T(R0,R1,R2,R3,ADDR) \
    asm volatile("ldmatrix.sync.aligned.m8n8.x4.trans.shared.b16 {%0,%1,%2,%3},[%4];" \
        : "=r"(R0),"=r"(R1),"=r"(R2),"=r"(R3) : "r"(ADDR))
#define MMA(C0,C1,C2,C3,A0,A1,A2,A3,B0,B1) \
    asm volatile("mma.sync.aligned.m16n8k16.row.col.f32.f16.f16.f32 " \
        "{%0,%1,%2,%3},{%4,%5,%6,%7},{%8,%9},{%0,%1,%2,%3};" \
        : "+f"(C0),"+f"(C1),"+f"(C2),"+f"(C3) \
        : "r"(A0),"r"(A1),"r"(A2),"r"(A3),"r"(B0),"r"(B1))
#define CP_COMMIT() asm volatile("cp.async.commit_group;")
#define CP_WAIT(N)  asm volatile("cp.async.wait_group %0;"::"n"(N))

// Stage one 128x32 fp16 weight chunk into wbuf slot (chunk&1) via cp.async.
// chunks 0..11 = Wqkv 32-col chunks, chunks 12..15 = Wmerge 32-col chunks.
__device__ __forceinline__ void stage_chunk(int chunk, __half* wbuf, int tid)
{
    __half* dst = wbuf + (chunk & 1) * WB_STAGE;
    const __half* src; int pitch, col0;
    if (chunk < 12) { src = g_wqkv;   pitch = 384; col0 = chunk * 32; }
    else            { src = g_wmerge; pitch = 128; col0 = (chunk - 12) * 32; }
    #pragma unroll
    for (int t = 0; t < 4; t++) {
        int idx = tid + t * 128;
        int r = idx >> 2, cs = (idx & 3) << 3;
        uint32_t d = cvta_s(dst + r * WB_P + cs);
        asm volatile("cp.async.cg.shared.global [%0],[%1],16;"
                     :: "r"(d), "l"(src + r * pitch + col0 + cs));
    }
    CP_COMMIT();
}

__global__ void __launch_bounds__(128, 3)
rpmha_mma_kernel(const float* __restrict__ x,
                 const float* __restrict__ bqkv,
                 const float* __restrict__ bmerge,
                 const float* __restrict__ table,
                 float* __restrict__ out)
{
    extern __shared__ __half sh[];
    __half* qkv  = sh + QKV_OFF;
    __half* wbuf = sh + WB_OFF;
    float*  tb   = reinterpret_cast<float*>(sh + HALFS);

    const int tid = threadIdx.x, warp = tid >> 5, lane = tid & 31;
    // GEMM work split: warp owns rows wrow..wrow+31 (2 m-tiles) and a 16-col
    // sub-slice of each 32-col weight chunk (B fragments reused across both
    // m-tiles -> half the ldmatrix traffic).
    const int wrow  = (warp & 1) << 5;      // 0 or 32
    const int wcsel = (warp >> 1) << 4;     // 0 or 16 (col offset in chunk)

    // kick off weight pipeline before touching x (overlap)
    stage_chunk(0, wbuf, tid);
    stage_chunk(1, wbuf, tid);

    // ---- stage x (fp32->fp16) into qkv v-region (cols 256..383), pad rows 0 ----
    const float* xg = x + (size_t)blockIdx.x * (PW * DD);
    #pragma unroll 4
    for (int idx = tid; idx < 2048; idx += 128) {
        int row = idx >> 5, c4 = (idx & 31) << 2;
        uint2 st;
        if (row < PW) {
            float4 f = *reinterpret_cast<const float4*>(xg + row * DD + c4);
            st.x = f2h2(f.x, f.y); st.y = f2h2(f.z, f.w);
        } else { st.x = 0u; st.y = 0u; }
        *reinterpret_cast<uint2*>(qkv + row * QKV_P + 256 + c4) = st;
    }
    for (int i = tid; i < 676; i += 128) tb[i] = table[i];
    __syncthreads();

    const uint32_t qkv_s = cvta_s(qkv);
    const float scale = 0.17677669529663687f;  // 1/sqrt(32)

    // ---- persistent A fragments: 2 m-tiles (rows wrow..wrow+31), K=128 ----
    uint32_t af[2][8][4];
    #pragma unroll
    for (int mt = 0; mt < 2; mt++) {
        uint32_t a0 = qkv_s + (((wrow + mt * 16) + (lane & 15)) * QKV_P
                               + 256 + ((lane >> 4) << 3)) * 2;
        #pragma unroll
        for (int kk = 0; kk < 8; kk++)
            LDSM4(af[mt][kk][0], af[mt][kk][1], af[mt][kk][2], af[mt][kk][3],
                  a0 + kk * 32);
    }

    // ===== Phase 1: qkv = x @ Wqkv + bqkv (12 x 32-col chunks, MxN warp split) =====
    for (int cn = 0; cn < 12; cn++) {
        CP_WAIT(1);            // chunk cn resident
        __syncthreads();

        float acc[2][2][4];    // [m-tile][n-tile(8col)][frag]
        #pragma unroll
        for (int nt = 0; nt < 2; nt++) {
            int col = cn * 32 + wcsel + nt * 8 + ((lane & 3) << 1);
            float b0 = __ldg(bqkv + col), b1 = __ldg(bqkv + col + 1);
            #pragma unroll
            for (int mt = 0; mt < 2; mt++) {
                acc[mt][nt][0] = b0; acc[mt][nt][1] = b1;
                acc[mt][nt][2] = b0; acc[mt][nt][3] = b1;
            }
        }
        uint32_t wb0 = cvta_s(wbuf + (cn & 1) * WB_STAGE)
                     + ((lane & 15) * WB_P + wcsel + ((lane >> 4) << 3)) * 2;
        #pragma unroll
        for (int kk = 0; kk < 8; kk++) {
            uint32_t b[4];
            LDSM4T(b[0], b[1], b[2], b[3], wb0 + (kk * 16 * WB_P) * 2);
            #pragma unroll
            for (int mt = 0; mt < 2; mt++) {
                MMA(acc[mt][0][0],acc[mt][0][1],acc[mt][0][2],acc[mt][0][3],
                    af[mt][kk][0],af[mt][kk][1],af[mt][kk][2],af[mt][kk][3],
                    b[0], b[1]);
                MMA(acc[mt][1][0],acc[mt][1][1],acc[mt][1][2],acc[mt][1][3],
                    af[mt][kk][0],af[mt][kk][1],af[mt][kk][2],af[mt][kk][3],
                    b[2], b[3]);
            }
        }
        const float mul = (cn < 4) ? scale : 1.0f;  // q cols < 128 pre-scaled
        #pragma unroll
        for (int mt = 0; mt < 2; mt++) {
            const int row = wrow + mt * 16 + (lane >> 2);
            #pragma unroll
            for (int nt = 0; nt < 2; nt++) {
                int col = cn * 32 + wcsel + nt * 8 + ((lane & 3) << 1);
                *reinterpret_cast<__half2*>(qkv + row * QKV_P + col) =
                    __floats2half2_rn(acc[mt][nt][0] * mul, acc[mt][nt][1] * mul);
                *reinterpret_cast<__half2*>(qkv + (row + 8) * QKV_P + col) =
                    __floats2half2_rn(acc[mt][nt][2] * mul, acc[mt][nt][3] * mul);
            }
        }
        __syncthreads();       // all warps done reading wbuf slot
        stage_chunk(cn + 2, wbuf, tid);
    }

    // ================= Phase 2: attention, warp = head =================
    {
        const int h = warp;

        uint32_t kb[7][4];
        #pragma unroll
        for (int nt = 0; nt < 7; nt++) {
            uint32_t addr = qkv_s + ((nt * 8 + (lane & 7)) * QKV_P
                                     + 128 + h * 32 + ((lane >> 3) << 3)) * 2;
            LDSM4(kb[nt][0], kb[nt][1], kb[nt][2], kb[nt][3], addr);
        }
        uint32_t vb[4][8];
        #pragma unroll
        for (int kt = 0; kt < 4; kt++)
            #pragma unroll
            for (int dp = 0; dp < 2; dp++) {
                uint32_t addr = qkv_s + ((kt * 16 + (lane & 15)) * QKV_P
                                         + 256 + h * 32 + dp * 16 + ((lane >> 4) << 3)) * 2;
                LDSM4T(vb[kt][dp*4+0], vb[kt][dp*4+1], vb[kt][dp*4+2], vb[kt][dp*4+3], addr);
            }

        #pragma unroll
        for (int m = 0; m < 4; m++) {
            uint32_t qa[4], qa2[4];
            uint32_t qaddr = qkv_s + ((m * 16 + (lane & 15)) * QKV_P
                                      + h * 32 + ((lane >> 4) << 3)) * 2;
            LDSM4(qa[0], qa[1], qa[2], qa[3], qaddr);
            LDSM4(qa2[0], qa2[1], qa2[2], qa2[3], qaddr + 32);

            float s[7][4];
            #pragma unroll
            for (int nt = 0; nt < 7; nt++) {
                s[nt][0] = s[nt][1] = s[nt][2] = s[nt][3] = 0.f;
                MMA(s[nt][0],s[nt][1],s[nt][2],s[nt][3],
                    qa[0],qa[1],qa[2],qa[3], kb[nt][0], kb[nt][1]);
                MMA(s[nt][0],s[nt][1],s[nt][2],s[nt][3],
                    qa2[0],qa2[1],qa2[2],qa2[3], kb[nt][2], kb[nt][3]);
            }

            // relative position bias + j-mask
            int i0 = m * 16 + (lane >> 2), i1 = i0 + 8;
            int i0c = (i0 < PW) ? i0 : 0, i1c = (i1 < PW) ? i1 : 0;
            int r0 = (i0c * 147) >> 10, c0i = i0c - r0 * 7;
            int r1 = (i1c * 147) >> 10, c1i = i1c - r1 * 7;
            #pragma unroll
            for (int nt = 0; nt < 7; nt++) {
                #pragma unroll
                for (int e = 0; e < 2; e++) {
                    int j = nt * 8 + ((lane & 3) << 1) + e;
                    if (j < PW) {
                        int rj = (j * 147) >> 10, cj = j - rj * 7;
                        s[nt][e]   += tb[(((r0 - rj + 6) * 13) + (c0i - cj + 6)) * 4 + h];
                        s[nt][2+e] += tb[(((r1 - rj + 6) * 13) + (c1i - cj + 6)) * 4 + h];
                    } else {
                        s[nt][e] = -1e30f; s[nt][2+e] = -1e30f;
                    }
                }
            }

            float ml = -1e30f, mh = -1e30f;
            #pragma unroll
            for (int nt = 0; nt < 7; nt++) {
                ml = fmaxf(ml, fmaxf(s[nt][0], s[nt][1]));
                mh = fmaxf(mh, fmaxf(s[nt][2], s[nt][3]));
            }
            ml = fmaxf(ml, __shfl_xor_sync(0xffffffffu, ml, 1));
            ml = fmaxf(ml, __shfl_xor_sync(0xffffffffu, ml, 2));
            mh = fmaxf(mh, __shfl_xor_sync(0xffffffffu, mh, 1));
            mh = fmaxf(mh, __shfl_xor_sync(0xffffffffu, mh, 2));
            float sl = 0.f, shs = 0.f;
            #pragma unroll
            for (int nt = 0; nt < 7; nt++) {
                s[nt][0] = __expf(s[nt][0] - ml); sl  += s[nt][0];
                s[nt][1] = __expf(s[nt][1] - ml); sl  += s[nt][1];
                s[nt][2] = __expf(s[nt][2] - mh); shs += s[nt][2];
                s[nt][3] = __expf(s[nt][3] - mh); shs += s[nt][3];
            }
            sl  += __shfl_xor_sync(0xffffffffu, sl, 1);
            sl  += __shfl_xor_sync(0xffffffffu, sl, 2);
            shs += __shfl_xor_sync(0xffffffffu, shs, 1);
            shs += __shfl_xor_sync(0xffffffffu, shs, 2);
            const float il = 1.f / sl, ih = 1.f / shs;

            uint32_t pa[4][4];
            #pragma unroll
            for (int kt = 0; kt < 4; kt++) {
                int n0 = 2 * kt, n1 = 2 * kt + 1;
                pa[kt][0] = f2h2(s[n0][0] * il, s[n0][1] * il);
                pa[kt][1] = f2h2(s[n0][2] * ih, s[n0][3] * ih);
                if (n1 < 7) {
                    pa[kt][2] = f2h2(s[n1][0] * il, s[n1][1] * il);
                    pa[kt][3] = f2h2(s[n1][2] * ih, s[n1][3] * ih);
                } else { pa[kt][2] = 0u; pa[kt][3] = 0u; }
            }

            float o[4][4];
            #pragma unroll
            for (int d = 0; d < 4; d++) o[d][0]=o[d][1]=o[d][2]=o[d][3]=0.f;
            #pragma unroll
            for (int kt = 0; kt < 4; kt++) {
                MMA(o[0][0],o[0][1],o[0][2],o[0][3],
                    pa[kt][0],pa[kt][1],pa[kt][2],pa[kt][3], vb[kt][0], vb[kt][1]);
                MMA(o[1][0],o[1][1],o[1][2],o[1][3],
                    pa[kt][0],pa[kt][1],pa[kt][2],pa[kt][3], vb[kt][2], vb[kt][3]);
                MMA(o[2][0],o[2][1],o[2][2],o[2][3],
                    pa[kt][0],pa[kt][1],pa[kt][2],pa[kt][3], vb[kt][4], vb[kt][5]);
                MMA(o[3][0],o[3][1],o[3][2],o[3][3],
                    pa[kt][0],pa[kt][1],pa[kt][2],pa[kt][3], vb[kt][6], vb[kt][7]);
            }
            // attn-out -> q region (warp=head owns cols 32h..32h+31 exclusively)
            const int orow = m * 16 + (lane >> 2);
            #pragma unroll
            for (int d = 0; d < 4; d++) {
                int col = h * 32 + d * 8 + ((lane & 3) << 1);
                *reinterpret_cast<__half2*>(qkv + orow * QKV_P + col) =
                    __floats2half2_rn(o[d][0], o[d][1]);
                *reinterpret_cast<__half2*>(qkv + (orow + 8) * QKV_P + col) =
                    __floats2half2_rn(o[d][2], o[d][3]);
            }
        }
    }
    __syncthreads();

    // ====== Phase 3: out = attn_out @ Wmerge + bmerge (4 chunks, MxN split) ======
    {
        uint32_t af2[2][8][4];
        #pragma unroll
        for (int mt = 0; mt < 2; mt++) {
            uint32_t a0 = qkv_s + (((wrow + mt * 16) + (lane & 15)) * QKV_P
                                   + ((lane >> 4) << 3)) * 2;
            #pragma unroll
            for (int kk = 0; kk < 8; kk++)
                LDSM4(af2[mt][kk][0], af2[mt][kk][1], af2[mt][kk][2], af2[mt][kk][3],
                      a0 + kk * 32);
        }

        float* obase = out + (size_t)blockIdx.x * (PW * DD);

        #pragma unroll
        for (int cm = 0; cm < 4; cm++) {
            if (cm < 3) { CP_WAIT(1); } else { CP_WAIT(0); }
            __syncthreads();

            float acc[2][2][4];
            #pragma unroll
            for (int nt = 0; nt < 2; nt++) {
                int col = cm * 32 + wcsel + nt * 8 + ((lane & 3) << 1);
                float b0 = __ldg(bmerge + col), b1 = __ldg(bmerge + col + 1);
                #pragma unroll
                for (int mt = 0; mt < 2; mt++) {
                    acc[mt][nt][0] = b0; acc[mt][nt][1] = b1;
                    acc[mt][nt][2] = b0; acc[mt][nt][3] = b1;
                }
            }
            uint32_t wb0 = cvta_s(wbuf + (cm & 1) * WB_STAGE)
                         + ((lane & 15) * WB_P + wcsel + ((lane >> 4) << 3)) * 2;
            #pragma unroll
            for (int kk = 0; kk < 8; kk++) {
                uint32_t b[4];
                LDSM4T(b[0], b[1], b[2], b[3], wb0 + (kk * 16 * WB_P) * 2);
                #pragma unroll
                for (int mt = 0; mt < 2; mt++) {
                    MMA(acc[mt][0][0],acc[mt][0][1],acc[mt][0][2],acc[mt][0][3],
                        af2[mt][kk][0],af2[mt][kk][1],af2[mt][kk][2],af2[mt][kk][3],
                        b[0], b[1]);
                    MMA(acc[mt][1][0],acc[mt][1][1],acc[mt][1][2],acc[mt][1][3],
                        af2[mt][kk][0],af2[mt][kk][1],af2[mt][kk][2],af2[mt][kk][3],
                        b[2], b[3]);
                }
            }
            #pragma unroll
            for (int mt = 0; mt < 2; mt++) {
                const int r0 = wrow + mt * 16 + (lane >> 2);
                #pragma unroll
                for (int nt = 0; nt < 2; nt++) {
                    int col = cm * 32 + wcsel + nt * 8 + ((lane & 3) << 1);
                    if (r0 < PW)
                        *reinterpret_cast<float2*>(obase + r0 * DD + col) =
                            make_float2(acc[mt][nt][0], acc[mt][nt][1]);
                    if (r0 + 8 < PW)
                        *reinterpret_cast<float2*>(obase + (r0 + 8) * DD + col) =
                            make_float2(acc[mt][nt][2], acc[mt][nt][3]);
                }
            }
            if (cm < 2) {
                __syncthreads();               // slot consumers done
                stage_chunk(cm + 14, wbuf, tid);
            }
        }
    }
}

extern "C" void kernel_launch(void* const* d_in, const int* in_sizes, int n_in,
                              void* d_out, int out_size)
{
    const float* x      = (const float*)d_in[0];
    const float* Wqkv   = (const float*)d_in[1];
    const float* bqkv   = (const float*)d_in[2];
    const float* Wmerge = (const float*)d_in[3];
    const float* bmerge = (const float*)d_in[4];
    const float* table  = (const float*)d_in[5];
    float* out = (float*)d_out;

    convert_w_kernel<<<192, 256>>>(Wqkv, Wmerge);

    const int nwin = in_sizes[0] / (PW * DD);   // 16384

    cudaFuncSetAttribute(rpmha_mma_kernel,
                         cudaFuncAttributeMaxDynamicSharedMemorySize, SMEM_BYTES);
    rpmha_mma_kernel<<<nwin, 128, SMEM_BYTES>>>(x, bqkv, bmerge, table, out);
}

// round 8
// speedup vs baseline: 10.2754x; 1.0061x over previous
#include <cuda_runtime.h>
#include <cuda_fp16.h>
#include <cstdint>
#include <math.h>

#define PW 49
#define DD 128

// ---------------- smem layout ----------------
// qkv [64][392] fp16 : v-region (cols 256..383) doubles as x target,
//                      q-region (cols 0..127) doubles as attn-out buffer
// wq  [128][392] fp16: resident Wqkv (cols 0..383)
// wm  [128][136] fp16: resident Wmerge (cols 0..127)
// tb  676 fp32       : relative-position bias table
// xs  [49][128] fp32 : x prefetch stage (cp.async target)
static constexpr int QKV_P  = 392;
static constexpr int WQ_P   = 392;
static constexpr int WM_P   = 136;
static constexpr int WQ_OFF = 64 * QKV_P;             // 25088 halfs
static constexpr int WM_OFF = WQ_OFF + 128 * WQ_P;    // 75264
static constexpr int HALFS  = WM_OFF + 128 * WM_P;    // 92672
static constexpr int TB_BYTE = HALFS * 2;             // 185344
static constexpr int XS_BYTE = TB_BYTE + 2704;        // 188048 (16B aligned)
static constexpr int SMEM_BYTES = XS_BYTE + PW * DD * 4;  // 213136

__device__ __forceinline__ uint32_t cvta_s(const void* p)
{
    return (uint32_t)__cvta_generic_to_shared(p);
}
__device__ __forceinline__ uint32_t f2h2(float a, float b)
{
    __half2 h = __floats2half2_rn(a, b);
    return *reinterpret_cast<uint32_t*>(&h);
}

#define LDSM4(R0,R1,R2,R3,ADDR) \
    asm volatile("ldmatrix.sync.aligned.m8n8.x4.shared.b16 {%0,%1,%2,%3},[%4];" \
        : "=r"(R0),"=r"(R1),"=r"(R2),"=r"(R3) : "r"(ADDR))
#define LDSM4T(R0,R1,R2,R3,ADDR) \
    asm volatile("ldmatrix.sync.aligned.m8n8.x4.trans.shared.b16 {%0,%1,%2,%3},[%4];" \
        : "=r"(R0),"=r"(R1),"=r"(R2),"=r"(R3) : "r"(ADDR))
#define MMA(C0,C1,C2,C3,A0,A1,A2,A3,B0,B1) \
    asm volatile("mma.sync.aligned.m16n8k16.row.col.f32.f16.f16.f32 " \
        "{%0,%1,%2,%3},{%4,%5,%6,%7},{%8,%9},{%0,%1,%2,%3};" \
        : "+f"(C0),"+f"(C1),"+f"(C2),"+f"(C3) \
        : "r"(A0),"r"(A1),"r"(A2),"r"(A3),"r"(B0),"r"(B1))
#define CP_COMMIT() asm volatile("cp.async.commit_group;")
#define CP_WAIT0()  asm volatile("cp.async.wait_group 0;")

__device__ __forceinline__ void prefetch_x(const float* __restrict__ x,
                                           int win, uint32_t xs_s, int tid)
{
    const float* src = x + (size_t)win * (PW * DD);
    #pragma unroll
    for (int t = 0; t < 7; t++) {
        int idx = tid + t * 256;
        if (idx < (PW * DD) / 4)
            asm volatile("cp.async.cg.shared.global [%0],[%1],16;"
                         :: "r"(xs_s + idx * 16), "l"(src + idx * 4));
    }
    CP_COMMIT();
}

__global__ void __launch_bounds__(256, 1)
rpmha_pers_kernel(const float* __restrict__ x,
                  const float* __restrict__ Wqkv,
                  const float* __restrict__ bqkv,
                  const float* __restrict__ Wmerge,
                  const float* __restrict__ bmerge,
                  const float* __restrict__ table,
                  float* __restrict__ out, int nwin)
{
    extern __shared__ __half sh[];
    __half* qkv = sh;
    __half* wq  = sh + WQ_OFF;
    __half* wm  = sh + WM_OFF;
    float*  tb  = reinterpret_cast<float*>(reinterpret_cast<char*>(sh) + TB_BYTE);
    float*  xs  = reinterpret_cast<float*>(reinterpret_cast<char*>(sh) + XS_BYTE);

    const int tid = threadIdx.x, warp = tid >> 5, lane = tid & 31;
    const uint32_t qkv_s = cvta_s(qkv);
    const uint32_t wq_s  = cvta_s(wq);
    const uint32_t wm_s  = cvta_s(wm);
    const uint32_t xs_s  = cvta_s(xs);
    const float scale = 0.17677669529663687f;  // 1/sqrt(32)

    // GEMM warp split: 2 (M) x 4 (N)
    const int wrow = (warp & 1) << 5;        // 0 / 32
    const int wq0  = (warp >> 1) * 96;       // phase-1 col base (96 cols/warp)
    const int wc   = (warp >> 1) << 5;       // phase-3 col base (32 cols/warp)
    // attention split: 2 warps per head
    const int ah = warp & 3, amh = warp >> 2;

    int win = blockIdx.x;
    if (win < nwin) prefetch_x(x, win, xs_s, tid);

    // ---- one-time: weights fp32 -> fp16 resident, bias table ----
    for (int i = tid; i < 128 * 384; i += 256) {
        int r = i / 384, c = i - r * 384;
        wq[r * WQ_P + c] = __float2half_rn(Wqkv[i]);
    }
    for (int i = tid; i < 128 * 128; i += 256) {
        int r = i >> 7, c = i & 127;
        wm[r * WM_P + c] = __float2half_rn(Wmerge[i]);
    }
    for (int i = tid; i < 676; i += 256) tb[i] = table[i];

    for (; win < nwin; win += gridDim.x) {
        CP_WAIT0();
        __syncthreads();                       // (1) x-stage ready, prev window done

        // ---- convert x (smem fp32) -> v-region fp16; zero pad rows ----
        #pragma unroll 4
        for (int idx = tid; idx < 2048; idx += 256) {
            int row = idx >> 5, c4 = (idx & 31) << 2;
            uint2 st;
            if (row < PW) {
                float4 f = *reinterpret_cast<const float4*>(xs + row * DD + c4);
                st.x = f2h2(f.x, f.y); st.y = f2h2(f.z, f.w);
            } else { st.x = 0u; st.y = 0u; }
            *reinterpret_cast<uint2*>(qkv + row * QKV_P + 256 + c4) = st;
        }
        __syncthreads();                       // (2) conversion done (x-stage free)

        if (win + (int)gridDim.x < nwin)
            prefetch_x(x, win + gridDim.x, xs_s, tid);   // overlaps all compute

        // ---- A fragments: rows wrow..wrow+31, K=128 (from v-region) ----
        uint32_t af[2][8][4];
        #pragma unroll
        for (int mt = 0; mt < 2; mt++) {
            uint32_t a0 = qkv_s + (((wrow + mt * 16) + (lane & 15)) * QKV_P
                                   + 256 + ((lane >> 4) << 3)) * 2;
            #pragma unroll
            for (int kk = 0; kk < 8; kk++)
                LDSM4(af[mt][kk][0], af[mt][kk][1], af[mt][kk][2], af[mt][kk][3],
                      a0 + kk * 32);
        }
        __syncthreads();                       // (3) A-frags safe before v writes

        // ================= Phase 1: qkv = x @ Wqkv + bqkv =================
        #pragma unroll
        for (int p = 0; p < 6; p++) {
            const int c0 = wq0 + p * 16;
            float acc[2][2][4];
            #pragma unroll
            for (int nt = 0; nt < 2; nt++) {
                int col = c0 + nt * 8 + ((lane & 3) << 1);
                float b0 = __ldg(bqkv + col), b1 = __ldg(bqkv + col + 1);
                #pragma unroll
                for (int mt = 0; mt < 2; mt++) {
                    acc[mt][nt][0] = b0; acc[mt][nt][1] = b1;
                    acc[mt][nt][2] = b0; acc[mt][nt][3] = b1;
                }
            }
            uint32_t wb0 = wq_s + ((lane & 15) * WQ_P + c0 + ((lane >> 4) << 3)) * 2;
            #pragma unroll
            for (int kk = 0; kk < 8; kk++) {
                uint32_t b[4];
                LDSM4T(b[0], b[1], b[2], b[3], wb0 + (kk * 16 * WQ_P) * 2);
                #pragma unroll
                for (int mt = 0; mt < 2; mt++) {
                    MMA(acc[mt][0][0],acc[mt][0][1],acc[mt][0][2],acc[mt][0][3],
                        af[mt][kk][0],af[mt][kk][1],af[mt][kk][2],af[mt][kk][3],
                        b[0], b[1]);
                    MMA(acc[mt][1][0],acc[mt][1][1],acc[mt][1][2],acc[mt][1][3],
                        af[mt][kk][0],af[mt][kk][1],af[mt][kk][2],af[mt][kk][3],
                        b[2], b[3]);
                }
            }
            const float mul = (c0 < 128) ? scale : 1.0f;
            #pragma unroll
            for (int mt = 0; mt < 2; mt++) {
                const int row = wrow + mt * 16 + (lane >> 2);
                #pragma unroll
                for (int nt = 0; nt < 2; nt++) {
                    int col = c0 + nt * 8 + ((lane & 3) << 1);
                    *reinterpret_cast<__half2*>(qkv + row * QKV_P + col) =
                        __floats2half2_rn(acc[mt][nt][0] * mul, acc[mt][nt][1] * mul);
                    *reinterpret_cast<__half2*>(qkv + (row + 8) * QKV_P + col) =
                        __floats2half2_rn(acc[mt][nt][2] * mul, acc[mt][nt][3] * mul);
                }
            }
        }
        __syncthreads();                       // (4) qkv complete

        // ============ Phase 2: attention (2 warps per head) ============
        {
            const int h = ah;
            uint32_t kb[7][4];
            #pragma unroll
            for (int nt = 0; nt < 7; nt++) {
                uint32_t addr = qkv_s + ((nt * 8 + (lane & 7)) * QKV_P
                                         + 128 + h * 32 + ((lane >> 3) << 3)) * 2;
                LDSM4(kb[nt][0], kb[nt][1], kb[nt][2], kb[nt][3], addr);
            }
            uint32_t vb[4][8];
            #pragma unroll
            for (int kt = 0; kt < 4; kt++)
                #pragma unroll
                for (int dp = 0; dp < 2; dp++) {
                    uint32_t addr = qkv_s + ((kt * 16 + (lane & 15)) * QKV_P
                                             + 256 + h * 32 + dp * 16 + ((lane >> 4) << 3)) * 2;
                    LDSM4T(vb[kt][dp*4+0], vb[kt][dp*4+1], vb[kt][dp*4+2], vb[kt][dp*4+3], addr);
                }

            #pragma unroll
            for (int mi = 0; mi < 2; mi++) {
                const int m = amh * 2 + mi;
                uint32_t qa[4], qa2[4];
                uint32_t qaddr = qkv_s + ((m * 16 + (lane & 15)) * QKV_P
                                          + h * 32 + ((lane >> 4) << 3)) * 2;
                LDSM4(qa[0], qa[1], qa[2], qa[3], qaddr);
                LDSM4(qa2[0], qa2[1], qa2[2], qa2[3], qaddr + 32);

                float s[7][4];
                #pragma unroll
                for (int nt = 0; nt < 7; nt++) {
                    s[nt][0] = s[nt][1] = s[nt][2] = s[nt][3] = 0.f;
                    MMA(s[nt][0],s[nt][1],s[nt][2],s[nt][3],
                        qa[0],qa[1],qa[2],qa[3], kb[nt][0], kb[nt][1]);
                    MMA(s[nt][0],s[nt][1],s[nt][2],s[nt][3],
                        qa2[0],qa2[1],qa2[2],qa2[3], kb[nt][2], kb[nt][3]);
                }

                int i0 = m * 16 + (lane >> 2), i1 = i0 + 8;
                int i0c = (i0 < PW) ? i0 : 0, i1c = (i1 < PW) ? i1 : 0;
                int r0 = (i0c * 147) >> 10, c0i = i0c - r0 * 7;
                int r1 = (i1c * 147) >> 10, c1i = i1c - r1 * 7;
                #pragma unroll
                for (int nt = 0; nt < 7; nt++) {
                    #pragma unroll
                    for (int e = 0; e < 2; e++) {
                        int j = nt * 8 + ((lane & 3) << 1) + e;
                        if (j < PW) {
                            int rj = (j * 147) >> 10, cj = j - rj * 7;
                            s[nt][e]   += tb[(((r0 - rj + 6) * 13) + (c0i - cj + 6)) * 4 + h];
                            s[nt][2+e] += tb[(((r1 - rj + 6) * 13) + (c1i - cj + 6)) * 4 + h];
                        } else {
                            s[nt][e] = -1e30f; s[nt][2+e] = -1e30f;
                        }
                    }
                }

                float ml = -1e30f, mh2 = -1e30f;
                #pragma unroll
                for (int nt = 0; nt < 7; nt++) {
                    ml  = fmaxf(ml,  fmaxf(s[nt][0], s[nt][1]));
                    mh2 = fmaxf(mh2, fmaxf(s[nt][2], s[nt][3]));
                }
                ml  = fmaxf(ml,  __shfl_xor_sync(0xffffffffu, ml, 1));
                ml  = fmaxf(ml,  __shfl_xor_sync(0xffffffffu, ml, 2));
                mh2 = fmaxf(mh2, __shfl_xor_sync(0xffffffffu, mh2, 1));
                mh2 = fmaxf(mh2, __shfl_xor_sync(0xffffffffu, mh2, 2));
                float sl = 0.f, shs = 0.f;
                #pragma unroll
                for (int nt = 0; nt < 7; nt++) {
                    s[nt][0] = __expf(s[nt][0] - ml);  sl  += s[nt][0];
                    s[nt][1] = __expf(s[nt][1] - ml);  sl  += s[nt][1];
                    s[nt][2] = __expf(s[nt][2] - mh2); shs += s[nt][2];
                    s[nt][3] = __expf(s[nt][3] - mh2); shs += s[nt][3];
                }
                sl  += __shfl_xor_sync(0xffffffffu, sl, 1);
                sl  += __shfl_xor_sync(0xffffffffu, sl, 2);
                shs += __shfl_xor_sync(0xffffffffu, shs, 1);
                shs += __shfl_xor_sync(0xffffffffu, shs, 2);
                const float il = 1.f / sl, ih = 1.f / shs;

                uint32_t pa[4][4];
                #pragma unroll
                for (int kt = 0; kt < 4; kt++) {
                    int n0 = 2 * kt, n1 = 2 * kt + 1;
                    pa[kt][0] = f2h2(s[n0][0] * il, s[n0][1] * il);
                    pa[kt][1] = f2h2(s[n0][2] * ih, s[n0][3] * ih);
                    if (n1 < 7) {
                        pa[kt][2] = f2h2(s[n1][0] * il, s[n1][1] * il);
                        pa[kt][3] = f2h2(s[n1][2] * ih, s[n1][3] * ih);
                    } else { pa[kt][2] = 0u; pa[kt][3] = 0u; }
                }

                float o[4][4];
                #pragma unroll
                for (int d = 0; d < 4; d++) o[d][0]=o[d][1]=o[d][2]=o[d][3]=0.f;
                #pragma unroll
                for (int kt = 0; kt < 4; kt++) {
                    MMA(o[0][0],o[0][1],o[0][2],o[0][3],
                        pa[kt][0],pa[kt][1],pa[kt][2],pa[kt][3], vb[kt][0], vb[kt][1]);
                    MMA(o[1][0],o[1][1],o[1][2],o[1][3],
                        pa[kt][0],pa[kt][1],pa[kt][2],pa[kt][3], vb[kt][2], vb[kt][3]);
                    MMA(o[2][0],o[2][1],o[2][2],o[2][3],
                        pa[kt][0],pa[kt][1],pa[kt][2],pa[kt][3], vb[kt][4], vb[kt][5]);
                    MMA(o[3][0],o[3][1],o[3][2],o[3][3],
                        pa[kt][0],pa[kt][1],pa[kt][2],pa[kt][3], vb[kt][6], vb[kt][7]);
                }
                const int orow = m * 16 + (lane >> 2);
                #pragma unroll
                for (int d = 0; d < 4; d++) {
                    int col = h * 32 + d * 8 + ((lane & 3) << 1);
                    *reinterpret_cast<__half2*>(qkv + orow * QKV_P + col) =
                        __floats2half2_rn(o[d][0], o[d][1]);
                    *reinterpret_cast<__half2*>(qkv + (orow + 8) * QKV_P + col) =
                        __floats2half2_rn(o[d][2], o[d][3]);
                }
            }
        }
        __syncthreads();                       // (5) attn-out in q-region

        // ============ Phase 3: out = attn_out @ Wmerge + bmerge ============
        {
            uint32_t af2[2][8][4];
            #pragma unroll
            for (int mt = 0; mt < 2; mt++) {
                uint32_t a0 = qkv_s + (((wrow + mt * 16) + (lane & 15)) * QKV_P
                                       + ((lane >> 4) << 3)) * 2;
                #pragma unroll
                for (int kk = 0; kk < 8; kk++)
                    LDSM4(af2[mt][kk][0], af2[mt][kk][1], af2[mt][kk][2], af2[mt][kk][3],
                          a0 + kk * 32);
            }

            float acc[2][4][4];
            #pragma unroll
            for (int nt = 0; nt < 4; nt++) {
                int col = wc + nt * 8 + ((lane & 3) << 1);
                float b0 = __ldg(bmerge + col), b1 = __ldg(bmerge + col + 1);
                #pragma unroll
                for (int mt = 0; mt < 2; mt++) {
                    acc[mt][nt][0] = b0; acc[mt][nt][1] = b1;
                    acc[mt][nt][2] = b0; acc[mt][nt][3] = b1;
                }
            }
            uint32_t wm0 = wm_s + ((lane & 15) * WM_P + wc + ((lane >> 4) << 3)) * 2;
            #pragma unroll
            for (int kk = 0; kk < 8; kk++) {
                uint32_t b[2][4];
                LDSM4T(b[0][0], b[0][1], b[0][2], b[0][3], wm0 + (kk * 16 * WM_P) * 2);
                LDSM4T(b[1][0], b[1][1], b[1][2], b[1][3], wm0 + (kk * 16 * WM_P + 16) * 2);
                #pragma unroll
                for (int mt = 0; mt < 2; mt++) {
                    MMA(acc[mt][0][0],acc[mt][0][1],acc[mt][0][2],acc[mt][0][3],
                        af2[mt][kk][0],af2[mt][kk][1],af2[mt][kk][2],af2[mt][kk][3],
                        b[0][0], b[0][1]);
                    MMA(acc[mt][1][0],acc[mt][1][1],acc[mt][1][2],acc[mt][1][3],
                        af2[mt][kk][0],af2[mt][kk][1],af2[mt][kk][2],af2[mt][kk][3],
                        b[0][2], b[0][3]);
                    MMA(acc[mt][2][0],acc[mt][2][1],acc[mt][2][2],acc[mt][2][3],
                        af2[mt][kk][0],af2[mt][kk][1],af2[mt][kk][2],af2[mt][kk][3],
                        b[1][0], b[1][1]);
                    MMA(acc[mt][3][0],acc[mt][3][1],acc[mt][3][2],acc[mt][3][3],
                        af2[mt][kk][0],af2[mt][kk][1],af2[mt][kk][2],af2[mt][kk][3],
                        b[1][2], b[1][3]);
                }
            }
            float* obase = out + (size_t)win * (PW * DD);
            #pragma unroll
            for (int mt = 0; mt < 2; mt++) {
                const int r0 = wrow + mt * 16 + (lane >> 2);
                #pragma unroll
                for (int nt = 0; nt < 4; nt++) {
                    int col = wc + nt * 8 + ((lane & 3) << 1);
                    if (r0 < PW)
                        *reinterpret_cast<float2*>(obase + r0 * DD + col) =
                            make_float2(acc[mt][nt][0], acc[mt][nt][1]);
                    if (r0 + 8 < PW)
                        *reinterpret_cast<float2*>(obase + (r0 + 8) * DD + col) =
                            make_float2(acc[mt][nt][2], acc[mt][nt][3]);
                }
            }
        }
    }
}

extern "C" void kernel_launch(void* const* d_in, const int* in_sizes, int n_in,
                              void* d_out, int out_size)
{
    const float* x      = (const float*)d_in[0];
    const float* Wqkv   = (const float*)d_in[1];
    const float* bqkv   = (const float*)d_in[2];
    const float* Wmerge = (const float*)d_in[3];
    const float* bmerge = (const float*)d_in[4];
    const float* table  = (const float*)d_in[5];
    float* out = (float*)d_out;

    const int nwin = in_sizes[0] / (PW * DD);   // 16384

    int sms = 148;
    cudaDeviceGetAttribute(&sms, cudaDevAttrMultiProcessorCount, 0);

    cudaFuncSetAttribute(rpmha_pers_kernel,
                         cudaFuncAttributeMaxDynamicSharedMemorySize, SMEM_BYTES);
    rpmha_pers_kernel<<<sms, 256, SMEM_BYTES>>>(x, Wqkv, bqkv, Wmerge, bmerge,
                                                table, out, nwin);
}